// round 1
// baseline (speedup 1.0000x reference)
#include <cuda_runtime.h>
#include <math.h>

#define NA_  100000
#define NP_  200000
#define FEAT_ 128
#define DD    32
#define EW_  1000000
#define EWB_ 1000000
#define EC_  2000000

// ---------------- scratch (device globals; no allocation allowed) ----------
__device__ float g_ka[NA_*DD], g_qa[NA_*DD], g_va[NA_*DD];
__device__ float g_kp[NP_*DD], g_qp[NP_*DD], g_vp[NP_*DD];
__device__ float g_krel[NP_*DD], g_vrel[NP_*DD];
__device__ float g_scores[EC_];
__device__ float g_smax[NP_], g_den[NP_];
__device__ float g_agg_a[NA_*DD], g_agg_p[NP_*DD];
__device__ float g_h1a[NA_*DD], g_h1p[NP_*DD];

// ---------------- helpers ---------------------------------------------------
__device__ __forceinline__ void atomicMaxF(float* addr, float v) {
    // signed-max / unsigned-min trick (valid for all finite floats & -inf init)
    if (v >= 0.0f) atomicMax((int*)addr, __float_as_int(v));
    else           atomicMin((unsigned int*)addr, __float_as_uint(v));
}

__device__ __forceinline__ void redAdd4(float* p, float a, float b, float c, float d) {
    asm volatile("red.global.add.v4.f32 [%0], {%1,%2,%3,%4};"
                 :: "l"(p), "f"(a), "f"(b), "f"(c), "f"(d) : "memory");
}

static inline int divup(int a, int b) { return (a + b - 1) / b; }

// ---------------- kernels ----------------------------------------------------

// k/q/v projection: warp handles 4 nodes, lane = output dim (32 dims).
// Each W element load serves 4 nodes (register tiling).
template<int F>
__global__ void kqv_kernel(const float* __restrict__ x,
                           const float* __restrict__ Wk, const float* __restrict__ bk,
                           const float* __restrict__ Wq, const float* __restrict__ bq,
                           const float* __restrict__ Wv, const float* __restrict__ bv,
                           float* __restrict__ k, float* __restrict__ q, float* __restrict__ v,
                           int n) {
    int gw   = (blockIdx.x * blockDim.x + threadIdx.x) >> 5;
    int lane = threadIdx.x & 31;
    int n0 = gw * 4;
    if (n0 >= n) return;
    int m = n - n0; if (m > 4) m = 4;

    float ak[4], aq[4], av[4];
#pragma unroll
    for (int j = 0; j < 4; j++) { ak[j] = bk[lane]; aq[j] = bq[lane]; av[j] = bv[lane]; }

    const float* x0 = x + (size_t)n0 * F;
#pragma unroll 4
    for (int i = 0; i < F; i++) {
        float wk = Wk[i * 32 + lane];
        float wq = Wq[i * 32 + lane];
        float wv = Wv[i * 32 + lane];
#pragma unroll
        for (int j = 0; j < 4; j++) {
            float xv = (j < m) ? __ldg(x0 + (size_t)j * F + i) : 0.0f;
            ak[j] = fmaf(xv, wk, ak[j]);
            aq[j] = fmaf(xv, wq, aq[j]);
            av[j] = fmaf(xv, wv, av[j]);
        }
    }
#pragma unroll
    for (int j = 0; j < 4; j++) {
        if (j < m) {
            size_t o = (size_t)(n0 + j) * 32 + lane;
            k[o] = ak[j]; q[o] = aq[j]; v[o] = av[j];
        }
    }
}

// per-relation transforms: krel = (k @ arel) * prel * 1/sqrt(d), vrel = v @ mrel
__global__ void rel_kernel(const float* __restrict__ k, const float* __restrict__ v,
                           const float* __restrict__ A, const float* __restrict__ M,
                           const float* __restrict__ prel, int r,
                           float* __restrict__ krel, float* __restrict__ vrel, int n) {
    int gw   = (blockIdx.x * blockDim.x + threadIdx.x) >> 5;
    int lane = threadIdx.x & 31;
    if (gw >= n) return;
    float ps = prel[r] * 0.17677669529663687f;  // 1/sqrt(32)
    size_t base = (size_t)gw * 32;
    float kl = k[base + lane];
    float vl = v[base + lane];
    float ak = 0.f, av = 0.f;
#pragma unroll
    for (int j = 0; j < 32; j++) {
        float kj = __shfl_sync(0xffffffffu, kl, j);
        float vj = __shfl_sync(0xffffffffu, vl, j);
        ak = fmaf(kj, A[j * 32 + lane], ak);
        av = fmaf(vj, M[j * 32 + lane], av);
    }
    krel[base + lane] = ak * ps;
    vrel[base + lane] = av;
}

__global__ void zero_kernel(float* __restrict__ p, int n) {
    int i = blockIdx.x * blockDim.x + threadIdx.x;
    if (i < n) p[i] = 0.0f;
}

__global__ void init_md_kernel(float* __restrict__ smax, float* __restrict__ den, int n) {
    int i = blockIdx.x * blockDim.x + threadIdx.x;
    if (i < n) { smax[i] = -INFINITY; den[i] = 0.0f; }
}

// score pass: 4 edges per warp, 8 lanes per edge, float4 gathers.
__global__ void score_kernel(const int* __restrict__ esrc, const int* __restrict__ edst,
                             const float* __restrict__ q, const float* __restrict__ krel,
                             float* __restrict__ scores, float* __restrict__ smax, int E) {
    int t    = blockIdx.x * blockDim.x + threadIdx.x;
    int gw   = t >> 5;
    int lane = threadIdx.x & 31;
    int sub  = lane >> 3;   // edge slot 0..3
    int ql   = lane & 7;    // quad index 0..7
    long e0 = (long)gw * 4 + sub;
    bool valid = (e0 < E);
    int e = valid ? (int)e0 : (E - 1);
    int src = __ldg(esrc + e);
    int dst = __ldg(edst + e);
    float4 a = __ldg((const float4*)(q    + (size_t)dst * 32) + ql);
    float4 b = __ldg((const float4*)(krel + (size_t)src * 32) + ql);
    float s = a.x * b.x + a.y * b.y + a.z * b.z + a.w * b.w;
    s += __shfl_xor_sync(0xffffffffu, s, 1);
    s += __shfl_xor_sync(0xffffffffu, s, 2);
    s += __shfl_xor_sync(0xffffffffu, s, 4);
    if (valid && ql == 0) {
        scores[e] = s;
        atomicMaxF(&smax[dst], s);
    }
}

// exp + denominator accumulation: one thread per edge.
__global__ void expsum_kernel(const int* __restrict__ edst,
                              float* __restrict__ scores,
                              const float* __restrict__ smax,
                              float* __restrict__ den, int E) {
    int e = blockIdx.x * blockDim.x + threadIdx.x;
    if (e >= E) return;
    int dst = __ldg(edst + e);
    float ex = expf(scores[e] - __ldg(smax + dst));
    scores[e] = ex;
    atomicAdd(&den[dst], ex);
}

// scatter pass: 4 edges per warp, 8 lanes per edge, vector red.add.v4.
__global__ void scatter_kernel(const int* __restrict__ esrc, const int* __restrict__ edst,
                               const float* __restrict__ vrel,
                               const float* __restrict__ scores,
                               const float* __restrict__ den,
                               float* __restrict__ agg, int E) {
    int t    = blockIdx.x * blockDim.x + threadIdx.x;
    int gw   = t >> 5;
    int lane = threadIdx.x & 31;
    int sub  = lane >> 3;
    int ql   = lane & 7;
    long e0 = (long)gw * 4 + sub;
    bool valid = (e0 < E);
    int e = valid ? (int)e0 : (E - 1);
    int src = __ldg(esrc + e);
    int dst = __ldg(edst + e);
    float alpha = __ldg(scores + e) / __ldg(den + dst);
    float4 vv = __ldg((const float4*)(vrel + (size_t)src * 32) + ql);
    if (valid) {
        redAdd4(agg + (size_t)dst * 32 + (size_t)ql * 4,
                vv.x * alpha, vv.y * alpha, vv.z * alpha, vv.w * alpha);
    }
}

// output transform: o = gelu(agg) @ Wa + ba, optional gated skip.
__global__ void out_kernel(const float* __restrict__ agg,
                           const float* __restrict__ Wa, const float* __restrict__ ba,
                           const float* __restrict__ skipv, int t_idx,
                           const float* __restrict__ xin,
                           float* __restrict__ out, int n, int use_skip) {
    int gw   = (blockIdx.x * blockDim.x + threadIdx.x) >> 5;
    int lane = threadIdx.x & 31;
    if (gw >= n) return;
    size_t base = (size_t)gw * 32;
    float x = agg[base + lane];
    float g = 0.5f * x * (1.0f + erff(x * 0.7071067811865475f));  // exact gelu
    float acc = ba[lane];
#pragma unroll
    for (int j = 0; j < 32; j++) {
        float gv = __shfl_sync(0xffffffffu, g, j);
        acc = fmaf(gv, Wa[j * 32 + lane], acc);
    }
    if (use_skip) {
        float a = 1.0f / (1.0f + expf(-skipv[t_idx]));
        acc = a * acc + (1.0f - a) * xin[base + lane];
    }
    out[base + lane] = acc;
}

// ---------------- host orchestration ----------------------------------------

struct RelDesc { const int* edges; int E; int s; int t; };

static void run_layer(const float* xa, const float* xp, int F,
                      const float* Wk, const float* bk,
                      const float* Wq, const float* bq,
                      const float* Wv, const float* bv,
                      const float* Wa, const float* ba,
                      const float* skip, const float* arel, const float* mrel,
                      const float* prel, int use_skip,
                      const RelDesc* rels,
                      float* ka, float* qa, float* va,
                      float* kp, float* qp, float* vp,
                      float* krel, float* vrel, float* scores,
                      float* smax, float* den,
                      float* agga, float* aggp,
                      float* outa, float* outp) {
    const int BT = 256;
    // k/q/v projections (per-type weight slices)
    int wsz = F * 32;
    if (F == 128) {
        kqv_kernel<128><<<divup(divup(NA_,4)*32, BT), BT>>>(xa, Wk, bk, Wq, bq, Wv, bv, ka, qa, va, NA_);
        kqv_kernel<128><<<divup(divup(NP_,4)*32, BT), BT>>>(xp, Wk+wsz, bk+32, Wq+wsz, bq+32, Wv+wsz, bv+32, kp, qp, vp, NP_);
    } else {
        kqv_kernel<32><<<divup(divup(NA_,4)*32, BT), BT>>>(xa, Wk, bk, Wq, bq, Wv, bv, ka, qa, va, NA_);
        kqv_kernel<32><<<divup(divup(NP_,4)*32, BT), BT>>>(xp, Wk+wsz, bk+32, Wq+wsz, bq+32, Wv+wsz, bv+32, kp, qp, vp, NP_);
    }
    zero_kernel<<<divup(NA_*32, BT), BT>>>(agga, NA_*32);
    zero_kernel<<<divup(NP_*32, BT), BT>>>(aggp, NP_*32);

    for (int r = 0; r < 3; r++) {
        const RelDesc& rd = rels[r];
        const float* ksrc = (rd.s == 0) ? ka : kp;
        const float* vsrc = (rd.s == 0) ? va : vp;
        const float* qdst = (rd.t == 0) ? qa : qp;
        float* agg        = (rd.t == 0) ? agga : aggp;
        int nsrc = (rd.s == 0) ? NA_ : NP_;
        int ndst = (rd.t == 0) ? NA_ : NP_;
        const int* esrc = rd.edges;
        const int* edst = rd.edges + rd.E;

        rel_kernel<<<divup(nsrc*32, BT), BT>>>(ksrc, vsrc, arel + r*32*32, mrel + r*32*32,
                                               prel, r, krel, vrel, nsrc);
        init_md_kernel<<<divup(ndst, BT), BT>>>(smax, den, ndst);

        int warps = divup(rd.E, 4);
        int blocks = divup(warps * 32, BT);
        score_kernel<<<blocks, BT>>>(esrc, edst, qdst, krel, scores, smax, rd.E);
        expsum_kernel<<<divup(rd.E, BT), BT>>>(edst, scores, smax, den, rd.E);
        scatter_kernel<<<blocks, BT>>>(esrc, edst, vrel, scores, den, agg, rd.E);
    }

    out_kernel<<<divup(NA_*32, BT), BT>>>(agga, Wa,        ba,     skip, 0, xa, outa, NA_, use_skip);
    out_kernel<<<divup(NP_*32, BT), BT>>>(aggp, Wa + 32*32, ba+32, skip, 1, xp, outp, NP_, use_skip);
}

extern "C" void kernel_launch(void* const* d_in, const int* in_sizes, int n_in,
                              void* d_out, int out_size) {
    const float* x_a   = (const float*)d_in[0];
    const float* x_p   = (const float*)d_in[1];
    const int* e_wr    = (const int*)d_in[2];
    const int* e_wb    = (const int*)d_in[3];
    const int* e_ci    = (const int*)d_in[4];
    const float* Wk1 = (const float*)d_in[5];  const float* bk1 = (const float*)d_in[6];
    const float* Wq1 = (const float*)d_in[7];  const float* bq1 = (const float*)d_in[8];
    const float* Wv1 = (const float*)d_in[9];  const float* bv1 = (const float*)d_in[10];
    const float* Wa1 = (const float*)d_in[11]; const float* ba1 = (const float*)d_in[12];
    const float* skip1 = (const float*)d_in[13];
    const float* arel1 = (const float*)d_in[14];
    const float* mrel1 = (const float*)d_in[15];
    const float* prel1 = (const float*)d_in[16];
    const float* Wk2 = (const float*)d_in[17]; const float* bk2 = (const float*)d_in[18];
    const float* Wq2 = (const float*)d_in[19]; const float* bq2 = (const float*)d_in[20];
    const float* Wv2 = (const float*)d_in[21]; const float* bv2 = (const float*)d_in[22];
    const float* Wa2 = (const float*)d_in[23]; const float* ba2 = (const float*)d_in[24];
    const float* skip2 = (const float*)d_in[25];
    const float* arel2 = (const float*)d_in[26];
    const float* mrel2 = (const float*)d_in[27];
    const float* prel2 = (const float*)d_in[28];

    float *ka,*qa,*va,*kp,*qp,*vp,*krel,*vrel,*scores,*smax,*den,*agga,*aggp,*h1a,*h1p;
    cudaGetSymbolAddress((void**)&ka,  g_ka);
    cudaGetSymbolAddress((void**)&qa,  g_qa);
    cudaGetSymbolAddress((void**)&va,  g_va);
    cudaGetSymbolAddress((void**)&kp,  g_kp);
    cudaGetSymbolAddress((void**)&qp,  g_qp);
    cudaGetSymbolAddress((void**)&vp,  g_vp);
    cudaGetSymbolAddress((void**)&krel, g_krel);
    cudaGetSymbolAddress((void**)&vrel, g_vrel);
    cudaGetSymbolAddress((void**)&scores, g_scores);
    cudaGetSymbolAddress((void**)&smax, g_smax);
    cudaGetSymbolAddress((void**)&den,  g_den);
    cudaGetSymbolAddress((void**)&agga, g_agg_a);
    cudaGetSymbolAddress((void**)&aggp, g_agg_p);
    cudaGetSymbolAddress((void**)&h1a,  g_h1a);
    cudaGetSymbolAddress((void**)&h1p,  g_h1p);

    RelDesc rels[3] = {
        { e_wr, EW_,  0, 1 },   // writes: author -> paper
        { e_wb, EWB_, 1, 0 },   // written_by: paper -> author
        { e_ci, EC_,  1, 1 },   // cites: paper -> paper
    };

    // Layer 1: 128 -> 32, no skip. Outputs to h1a / h1p.
    run_layer(x_a, x_p, 128,
              Wk1, bk1, Wq1, bq1, Wv1, bv1, Wa1, ba1, skip1, arel1, mrel1, prel1, 0,
              rels, ka, qa, va, kp, qp, vp, krel, vrel, scores, smax, den,
              agga, aggp, h1a, h1p);

    // Layer 2: 32 -> 32, gated skip. Outputs to d_out (authors first, then papers).
    float* out = (float*)d_out;
    run_layer(h1a, h1p, 32,
              Wk2, bk2, Wq2, bq2, Wv2, bv2, Wa2, ba2, skip2, arel2, mrel2, prel2, 1,
              rels, ka, qa, va, kp, qp, vp, krel, vrel, scores, smax, den,
              agga, aggp, out, out + (size_t)NA_ * 32);
}

// round 3
// speedup vs baseline: 1.2797x; 1.2797x over previous
#include <cuda_runtime.h>
#include <math.h>

#define NA_  100000
#define NP_  200000
#define DD    32
#define EW_  1000000
#define EWB_ 1000000
#define EC_  2000000

// ---------------- scratch (device globals; no allocation allowed) ----------
__device__ float g_ka[NA_*DD], g_qa[NA_*DD], g_va[NA_*DD];
__device__ float g_kp[NP_*DD], g_qp[NP_*DD], g_vp[NP_*DD];
__device__ float g_krel[NP_*DD], g_vrel[NP_*DD];
// combined agg (N*32) + den (N) buffers, zeroed in one pass each
__device__ float g_ad_a[NA_*33];    // authors (relation: written_by)
__device__ float g_ad_pw[NP_*33];   // papers via writes
__device__ float g_ad_pc[NP_*33];   // papers via cites
__device__ float g_h1a[NA_*DD], g_h1p[NP_*DD];

// ---------------- helpers ---------------------------------------------------
__device__ __forceinline__ void redAdd4(float* p, float a, float b, float c, float d) {
    asm volatile("red.global.add.v4.f32 [%0], {%1,%2,%3,%4};"
                 :: "l"(p), "f"(a), "f"(b), "f"(c), "f"(d) : "memory");
}
__device__ __forceinline__ unsigned long long pack2(float lo, float hi) {
    unsigned long long r;
    asm("mov.b64 %0, {%1,%2};" : "=l"(r) : "f"(lo), "f"(hi));
    return r;
}
__device__ __forceinline__ void ffma2(unsigned long long& acc,
                                      unsigned long long a, unsigned long long b) {
    asm("fma.rn.f32x2 %0, %1, %2, %0;" : "+l"(acc) : "l"(a), "l"(b));
}
__device__ __forceinline__ float2 unpack2(unsigned long long v) {
    float2 r;
    asm("mov.b64 {%0,%1}, %2;" : "=f"(r.x), "=f"(r.y) : "l"(v));
    return r;
}
static inline int divup(int a, int b) { return (a + b - 1) / b; }

// ---------------- kernels ----------------------------------------------------

// k/q/v projection: warp handles 4 nodes, lane = output dim.
// W staged in smem (LDS), x preloaded as float4 + shuffled, f32x2 accumulation.
template<int F>
__global__ void kqv_kernel(const float* __restrict__ x,
                           const float* __restrict__ Wk, const float* __restrict__ bk,
                           const float* __restrict__ Wq, const float* __restrict__ bq,
                           const float* __restrict__ Wv, const float* __restrict__ bv,
                           float* __restrict__ k, float* __restrict__ q, float* __restrict__ v,
                           int n) {
    __shared__ float sWk[F*32], sWq[F*32], sWv[F*32];
    for (int i = threadIdx.x; i < F*32; i += blockDim.x) {
        sWk[i] = Wk[i]; sWq[i] = Wq[i]; sWv[i] = Wv[i];
    }
    __syncthreads();

    int lane = threadIdx.x & 31;
    int gw = blockIdx.x * (blockDim.x >> 5) + (threadIdx.x >> 5);
    int n0 = gw * 4;
    if (n0 >= n) return;
    int m = n - n0; if (m > 4) m = 4;

    // preload x rows: lane holds elements [lane*4, lane*4+4) of each node
    float4 xr[4];
#pragma unroll
    for (int j = 0; j < 4; j++) {
        if (j < m && lane * 4 < F)
            xr[j] = __ldg((const float4*)(x + (size_t)(n0 + j) * F) + lane);
        else
            xr[j] = make_float4(0.f, 0.f, 0.f, 0.f);
    }

    unsigned long long K01 = pack2(bk[lane], bk[lane]), K23 = K01;
    unsigned long long Q01 = pack2(bq[lane], bq[lane]), Q23 = Q01;
    unsigned long long V01 = pack2(bv[lane], bv[lane]), V23 = V01;

    for (int i0 = 0; i0 < F; i0 += 4) {
        int sl = i0 >> 2;
        float xs[4][4];
#pragma unroll
        for (int j = 0; j < 4; j++) {
            xs[j][0] = __shfl_sync(0xffffffffu, xr[j].x, sl);
            xs[j][1] = __shfl_sync(0xffffffffu, xr[j].y, sl);
            xs[j][2] = __shfl_sync(0xffffffffu, xr[j].z, sl);
            xs[j][3] = __shfl_sync(0xffffffffu, xr[j].w, sl);
        }
#pragma unroll
        for (int c = 0; c < 4; c++) {
            int i = i0 + c;
            float wk = sWk[i*32 + lane];
            float wq = sWq[i*32 + lane];
            float wv = sWv[i*32 + lane];
            unsigned long long wk2 = pack2(wk, wk);
            unsigned long long wq2 = pack2(wq, wq);
            unsigned long long wv2 = pack2(wv, wv);
            unsigned long long x01 = pack2(xs[0][c], xs[1][c]);
            unsigned long long x23 = pack2(xs[2][c], xs[3][c]);
            ffma2(K01, x01, wk2); ffma2(K23, x23, wk2);
            ffma2(Q01, x01, wq2); ffma2(Q23, x23, wq2);
            ffma2(V01, x01, wv2); ffma2(V23, x23, wv2);
        }
    }

    float2 k01 = unpack2(K01), k23 = unpack2(K23);
    float2 q01 = unpack2(Q01), q23 = unpack2(Q23);
    float2 v01 = unpack2(V01), v23 = unpack2(V23);
    float kk[4] = {k01.x, k01.y, k23.x, k23.y};
    float qq[4] = {q01.x, q01.y, q23.x, q23.y};
    float vv[4] = {v01.x, v01.y, v23.x, v23.y};
#pragma unroll
    for (int j = 0; j < 4; j++) {
        if (j < m) {
            size_t o = (size_t)(n0 + j) * 32 + lane;
            k[o] = kk[j]; q[o] = qq[j]; v[o] = vv[j];
        }
    }
}

// per-relation transforms: krel = (k @ arel) * prel / sqrt(d), vrel = v @ mrel
__global__ void rel_kernel(const float* __restrict__ k, const float* __restrict__ v,
                           const float* __restrict__ A, const float* __restrict__ M,
                           const float* __restrict__ prel, int r,
                           float* __restrict__ krel, float* __restrict__ vrel, int n) {
    int gw   = (blockIdx.x * blockDim.x + threadIdx.x) >> 5;
    int lane = threadIdx.x & 31;
    if (gw >= n) return;
    float ps = prel[r] * 0.17677669529663687f;  // 1/sqrt(32)
    size_t base = (size_t)gw * 32;
    float kl = k[base + lane];
    float vl = v[base + lane];
    float ak = 0.f, av = 0.f;
#pragma unroll
    for (int j = 0; j < 32; j++) {
        float kj = __shfl_sync(0xffffffffu, kl, j);
        float vj = __shfl_sync(0xffffffffu, vl, j);
        ak = fmaf(kj, A[j * 32 + lane], ak);
        av = fmaf(vj, M[j * 32 + lane], av);
    }
    krel[base + lane] = ak * ps;
    vrel[base + lane] = av;
}

__global__ void zero4_kernel(float4* __restrict__ p, int n4) {
    int i = blockIdx.x * blockDim.x + threadIdx.x;
    if (i < n4) p[i] = make_float4(0.f, 0.f, 0.f, 0.f);
}

// fused edge pass: score -> exp -> unnormalized scatter + den accumulation.
// 4 edges/warp, 8 lanes/edge, float4 gathers, vector RED scatter.
__global__ void edge_fused_kernel(const int* __restrict__ esrc, const int* __restrict__ edst,
                                  const float* __restrict__ q, const float* __restrict__ krel,
                                  const float* __restrict__ vrel,
                                  float* __restrict__ agg, float* __restrict__ den, int E) {
    int t    = blockIdx.x * blockDim.x + threadIdx.x;
    int gw   = t >> 5;
    int lane = threadIdx.x & 31;
    int sub  = lane >> 3;
    int ql   = lane & 7;
    long e0 = (long)gw * 4 + sub;
    bool valid = (e0 < E);
    int e = valid ? (int)e0 : (E - 1);
    int src = __ldg(esrc + e);
    int dst = __ldg(edst + e);
    float4 a  = __ldg((const float4*)(q    + (size_t)dst * 32) + ql);
    float4 b  = __ldg((const float4*)(krel + (size_t)src * 32) + ql);
    float4 vv = __ldg((const float4*)(vrel + (size_t)src * 32) + ql);
    float s = a.x * b.x + a.y * b.y + a.z * b.z + a.w * b.w;
    s += __shfl_xor_sync(0xffffffffu, s, 1);
    s += __shfl_xor_sync(0xffffffffu, s, 2);
    s += __shfl_xor_sync(0xffffffffu, s, 4);
    float ex = __expf(fminf(s, 60.0f));   // clamp is an overflow guard; never hit for this data
    if (valid) {
        redAdd4(agg + (size_t)dst * 32 + (size_t)ql * 4,
                vv.x * ex, vv.y * ex, vv.z * ex, vv.w * ex);
        if (ql == 0) atomicAdd(den + dst, ex);
    }
}

// output transform: o = gelu(sum_r agg_r/den_r) @ Wa + ba, optional gated skip.
__global__ void out_kernel(const float* __restrict__ agg1, const float* __restrict__ den1,
                           const float* __restrict__ agg2, const float* __restrict__ den2,
                           const float* __restrict__ Wa, const float* __restrict__ ba,
                           const float* __restrict__ skipv, int t_idx,
                           const float* __restrict__ xin,
                           float* __restrict__ out, int n, int use_skip) {
    int gw   = (blockIdx.x * blockDim.x + threadIdx.x) >> 5;
    int lane = threadIdx.x & 31;
    if (gw >= n) return;
    size_t base = (size_t)gw * 32;
    float x = 0.0f;
    float d1 = den1[gw];
    if (d1 > 0.0f) x += agg1[base + lane] / d1;
    if (agg2) {
        float d2 = den2[gw];
        if (d2 > 0.0f) x += agg2[base + lane] / d2;
    }
    float g = 0.5f * x * (1.0f + erff(x * 0.7071067811865475f));  // exact gelu
    float acc = ba[lane];
#pragma unroll
    for (int j = 0; j < 32; j++) {
        float gv = __shfl_sync(0xffffffffu, g, j);
        acc = fmaf(gv, Wa[j * 32 + lane], acc);
    }
    if (use_skip) {
        float a = 1.0f / (1.0f + expf(-skipv[t_idx]));
        acc = a * acc + (1.0f - a) * xin[base + lane];
    }
    out[base + lane] = acc;
}

// ---------------- host orchestration ----------------------------------------

static void run_layer(const float* xa, const float* xp, int F,
                      const float* Wk, const float* bk,
                      const float* Wq, const float* bq,
                      const float* Wv, const float* bv,
                      const float* Wa, const float* ba,
                      const float* skip, const float* arel, const float* mrel,
                      const float* prel, int use_skip,
                      const int* e_wr, const int* e_wb, const int* e_ci,
                      float* ka, float* qa, float* va,
                      float* kp, float* qp, float* vp,
                      float* krel, float* vrel,
                      float* ad_a, float* ad_pw, float* ad_pc,
                      float* outa, float* outp) {
    const int BT = 256;
    int wsz = F * 32;
    if (F == 128) {
        kqv_kernel<128><<<divup(divup(NA_,4)*32, BT), BT>>>(xa, Wk, bk, Wq, bq, Wv, bv, ka, qa, va, NA_);
        kqv_kernel<128><<<divup(divup(NP_,4)*32, BT), BT>>>(xp, Wk+wsz, bk+32, Wq+wsz, bq+32, Wv+wsz, bv+32, kp, qp, vp, NP_);
    } else {
        kqv_kernel<32><<<divup(divup(NA_,4)*32, BT), BT>>>(xa, Wk, bk, Wq, bq, Wv, bv, ka, qa, va, NA_);
        kqv_kernel<32><<<divup(divup(NP_,4)*32, BT), BT>>>(xp, Wk+wsz, bk+32, Wq+wsz, bq+32, Wv+wsz, bv+32, kp, qp, vp, NP_);
    }
    zero4_kernel<<<divup(NP_*33/4, BT), BT>>>((float4*)ad_pw, NP_*33/4);
    zero4_kernel<<<divup(NA_*33/4, BT), BT>>>((float4*)ad_a,  NA_*33/4);

    // r0: writes (author -> paper)
    rel_kernel<<<divup(NA_*32, BT), BT>>>(ka, va, arel + 0*1024, mrel + 0*1024, prel, 0, krel, vrel, NA_);
    {
        int blocks = divup(divup(EW_, 4) * 32, BT);
        edge_fused_kernel<<<blocks, BT>>>(e_wr, e_wr + EW_, qp, krel, vrel,
                                          ad_pw, ad_pw + (size_t)NP_*32, EW_);
    }
    // r1: written_by (paper -> author)
    rel_kernel<<<divup(NP_*32, BT), BT>>>(kp, vp, arel + 1*1024, mrel + 1*1024, prel, 1, krel, vrel, NP_);
    {
        int blocks = divup(divup(EWB_, 4) * 32, BT);
        edge_fused_kernel<<<blocks, BT>>>(e_wb, e_wb + EWB_, qa, krel, vrel,
                                          ad_a, ad_a + (size_t)NA_*32, EWB_);
    }
    // r2: cites (paper -> paper)
    zero4_kernel<<<divup(NP_*33/4, BT), BT>>>((float4*)ad_pc, NP_*33/4);
    rel_kernel<<<divup(NP_*32, BT), BT>>>(kp, vp, arel + 2*1024, mrel + 2*1024, prel, 2, krel, vrel, NP_);
    {
        int blocks = divup(divup(EC_, 4) * 32, BT);
        edge_fused_kernel<<<blocks, BT>>>(e_ci, e_ci + EC_, qp, krel, vrel,
                                          ad_pc, ad_pc + (size_t)NP_*32, EC_);
    }

    out_kernel<<<divup(NA_*32, BT), BT>>>(ad_a, ad_a + (size_t)NA_*32, (const float*)0, (const float*)0,
                                          Wa, ba, skip, 0, xa, outa, NA_, use_skip);
    out_kernel<<<divup(NP_*32, BT), BT>>>(ad_pw, ad_pw + (size_t)NP_*32, ad_pc, ad_pc + (size_t)NP_*32,
                                          Wa + 1024, ba + 32, skip, 1, xp, outp, NP_, use_skip);
}

extern "C" void kernel_launch(void* const* d_in, const int* in_sizes, int n_in,
                              void* d_out, int out_size) {
    const float* x_a   = (const float*)d_in[0];
    const float* x_p   = (const float*)d_in[1];
    const int* e_wr    = (const int*)d_in[2];
    const int* e_wb    = (const int*)d_in[3];
    const int* e_ci    = (const int*)d_in[4];
    const float* Wk1 = (const float*)d_in[5];  const float* bk1 = (const float*)d_in[6];
    const float* Wq1 = (const float*)d_in[7];  const float* bq1 = (const float*)d_in[8];
    const float* Wv1 = (const float*)d_in[9];  const float* bv1 = (const float*)d_in[10];
    const float* Wa1 = (const float*)d_in[11]; const float* ba1 = (const float*)d_in[12];
    const float* skip1 = (const float*)d_in[13];
    const float* arel1 = (const float*)d_in[14];
    const float* mrel1 = (const float*)d_in[15];
    const float* prel1 = (const float*)d_in[16];
    const float* Wk2 = (const float*)d_in[17]; const float* bk2 = (const float*)d_in[18];
    const float* Wq2 = (const float*)d_in[19]; const float* bq2 = (const float*)d_in[20];
    const float* Wv2 = (const float*)d_in[21]; const float* bv2 = (const float*)d_in[22];
    const float* Wa2 = (const float*)d_in[23]; const float* ba2 = (const float*)d_in[24];
    const float* skip2 = (const float*)d_in[25];
    const float* arel2 = (const float*)d_in[26];
    const float* mrel2 = (const float*)d_in[27];
    const float* prel2 = (const float*)d_in[28];

    float *ka,*qa,*va,*kp,*qp,*vp,*krel,*vrel,*ad_a,*ad_pw,*ad_pc,*h1a,*h1p;
    cudaGetSymbolAddress((void**)&ka,  g_ka);
    cudaGetSymbolAddress((void**)&qa,  g_qa);
    cudaGetSymbolAddress((void**)&va,  g_va);
    cudaGetSymbolAddress((void**)&kp,  g_kp);
    cudaGetSymbolAddress((void**)&qp,  g_qp);
    cudaGetSymbolAddress((void**)&vp,  g_vp);
    cudaGetSymbolAddress((void**)&krel, g_krel);
    cudaGetSymbolAddress((void**)&vrel, g_vrel);
    cudaGetSymbolAddress((void**)&ad_a,  g_ad_a);
    cudaGetSymbolAddress((void**)&ad_pw, g_ad_pw);
    cudaGetSymbolAddress((void**)&ad_pc, g_ad_pc);
    cudaGetSymbolAddress((void**)&h1a,  g_h1a);
    cudaGetSymbolAddress((void**)&h1p,  g_h1p);

    // Layer 1: 128 -> 32, no skip.
    run_layer(x_a, x_p, 128,
              Wk1, bk1, Wq1, bq1, Wv1, bv1, Wa1, ba1, skip1, arel1, mrel1, prel1, 0,
              e_wr, e_wb, e_ci,
              ka, qa, va, kp, qp, vp, krel, vrel, ad_a, ad_pw, ad_pc, h1a, h1p);

    // Layer 2: 32 -> 32, gated skip. Outputs to d_out (authors first, then papers).
    float* out = (float*)d_out;
    run_layer(h1a, h1p, 32,
              Wk2, bk2, Wq2, bq2, Wv2, bv2, Wa2, ba2, skip2, arel2, mrel2, prel2, 1,
              e_wr, e_wb, e_ci,
              ka, qa, va, kp, qp, vp, krel, vrel, ad_a, ad_pw, ad_pc,
              out, out + (size_t)NA_ * 32);
}

// round 4
// speedup vs baseline: 1.6205x; 1.2663x over previous
#include <cuda_runtime.h>
#include <math.h>

#define NA_  100000
#define NP_  200000
#define EW_  1000000
#define EWB_ 1000000
#define EC_  2000000

// ---------------- scratch (device globals; no allocation allowed) ----------
__device__ float g_qa[NA_*32], g_qp[NP_*32];
__device__ float g_k0[NA_*32], g_v0[NA_*32];               // authors as src (rel 0)
__device__ float g_k1[NP_*32], g_v1[NP_*32];               // papers as src (rel 1)
__device__ float g_k2[NP_*32], g_v2[NP_*32];               // papers as src (rel 2)
__device__ float g_xa[NA_*32], g_xpw[NP_*32], g_xpc[NP_*32];
__device__ float g_h1a[NA_*32], g_h1p[NP_*32];
// CSR per relation (dst-indexed)
__device__ int g_deg_w[NP_], g_rp_w[NP_+1];  __device__ int g_cs_w[EW_];
__device__ int g_deg_b[NA_], g_rp_b[NA_+1];  __device__ int g_cs_b[EWB_];
__device__ int g_deg_c[NP_], g_rp_c[NP_+1];  __device__ int g_cs_c[EC_];
__device__ int g_bs_w[256], g_bs_b[256], g_bs_c[256];
// composite weights: kA0,vA0,kP1,vP1,kP2,vP2 (max F=128) + biases
__device__ float g_cW[6][128*32];
__device__ float g_cb[6][32];

// ---------------- helpers ---------------------------------------------------
__device__ __forceinline__ unsigned long long pack2(float lo, float hi) {
    unsigned long long r;
    asm("mov.b64 %0, {%1,%2};" : "=l"(r) : "f"(lo), "f"(hi));
    return r;
}
__device__ __forceinline__ void ffma2(unsigned long long& acc,
                                      unsigned long long a, unsigned long long b) {
    asm("fma.rn.f32x2 %0, %1, %2, %0;" : "+l"(acc) : "l"(a), "l"(b));
}
__device__ __forceinline__ float2 unpack2(unsigned long long v) {
    float2 r;
    asm("mov.b64 {%0,%1}, %2;" : "=f"(r.x), "=f"(r.y) : "l"(v));
    return r;
}
static inline int divup(int a, int b) { return (a + b - 1) / b; }

// ---------------- CSR build --------------------------------------------------
__global__ void zero_int_kernel(int* __restrict__ p, int n) {
    int i = blockIdx.x * blockDim.x + threadIdx.x;
    if (i < n) p[i] = 0;
}
__global__ void count_kernel(const int* __restrict__ dst, int E, int* __restrict__ deg) {
    int e = blockIdx.x * blockDim.x + threadIdx.x;
    if (e < E) atomicAdd(&deg[dst[e]], 1);
}
// block = 256 threads, 1024 elements per block
__global__ void scan_p1(const int* __restrict__ deg, int n, int* __restrict__ bsum) {
    __shared__ int sm[256];
    int base = blockIdx.x * 1024;
    int t = threadIdx.x;
    int s = 0;
#pragma unroll
    for (int j = 0; j < 4; j++) {
        int i = base + t * 4 + j;
        if (i < n) s += deg[i];
    }
    sm[t] = s; __syncthreads();
#pragma unroll
    for (int o = 128; o > 0; o >>= 1) {
        if (t < o) sm[t] += sm[t + o];
        __syncthreads();
    }
    if (t == 0) bsum[blockIdx.x] = sm[0];
}
__global__ void scan_p2(int* __restrict__ bsum, int nb, int* __restrict__ rp_last) {
    __shared__ int sm[256];
    int t = threadIdx.x;
    int v = (t < nb) ? bsum[t] : 0;
    sm[t] = v; __syncthreads();
    for (int o = 1; o < 256; o <<= 1) {
        int x = (t >= o) ? sm[t - o] : 0;
        __syncthreads();
        sm[t] += x;
        __syncthreads();
    }
    if (t < nb) bsum[t] = sm[t] - v;   // exclusive
    if (t == 255) *rp_last = sm[255];  // total
}
__global__ void scan_p3(const int* __restrict__ deg, int n, const int* __restrict__ bsum,
                        int* __restrict__ rp, int* __restrict__ cur) {
    __shared__ int sm[256];
    int base = blockIdx.x * 1024;
    int t = threadIdx.x;
    int v[4]; int s = 0;
#pragma unroll
    for (int j = 0; j < 4; j++) {
        int i = base + t * 4 + j;
        v[j] = (i < n) ? deg[i] : 0;
        s += v[j];
    }
    sm[t] = s; __syncthreads();
    for (int o = 1; o < 256; o <<= 1) {
        int x = (t >= o) ? sm[t - o] : 0;
        __syncthreads();
        sm[t] += x;
        __syncthreads();
    }
    int run = bsum[blockIdx.x] + sm[t] - s;
#pragma unroll
    for (int j = 0; j < 4; j++) {
        int i = base + t * 4 + j;
        if (i < n) { rp[i] = run; cur[i] = run; }
        run += v[j];
    }
}
__global__ void scatter_kernel(const int* __restrict__ src, const int* __restrict__ dst,
                               int E, int* __restrict__ cur, int* __restrict__ cs) {
    int e = blockIdx.x * blockDim.x + threadIdx.x;
    if (e < E) {
        int slot = atomicAdd(&cur[dst[e]], 1);
        cs[slot] = src[e];
    }
}

// ---------------- weight composition -----------------------------------------
// Wout[F,32] = W[F,32] @ T[32,32] * scale ; bout = b @ T * scale
// scale = prel ? prel[r]/sqrt(32) : 1
__global__ void compose_kernel(const float* __restrict__ W, const float* __restrict__ b,
                               const float* __restrict__ T, const float* __restrict__ prel,
                               int r, float* __restrict__ Wout, float* __restrict__ bout, int F) {
    int gw   = (blockIdx.x * blockDim.x + threadIdx.x) >> 5;
    int lane = threadIdx.x & 31;
    if (gw > F) return;
    float scale = prel ? (__ldg(prel + r) * 0.17677669529663687f) : 1.0f;
    const float* row = (gw < F) ? (W + (size_t)gw * 32) : b;
    float rv = row[lane];
    float acc = 0.f;
#pragma unroll
    for (int j = 0; j < 32; j++) {
        float rj = __shfl_sync(0xffffffffu, rv, j);
        acc = fmaf(rj, __ldg(T + j * 32 + lane), acc);
    }
    acc *= scale;
    if (gw < F) Wout[gw * 32 + lane] = acc;
    else        bout[lane] = acc;
}

// ---------------- projections -------------------------------------------------
// warp handles 4 nodes; lane = output dim. Wk/Wv staged in smem, Wq via LDG (L1).
template<int F>
__global__ void kqv3_kernel(const float* __restrict__ x,
                            const float* __restrict__ Wq, const float* __restrict__ bq,
                            const float* __restrict__ Wk, const float* __restrict__ bk,
                            const float* __restrict__ Wv, const float* __restrict__ bv,
                            float* __restrict__ q, float* __restrict__ k, float* __restrict__ v,
                            int n) {
    __shared__ float sWk[F*32], sWv[F*32];
    for (int i = threadIdx.x; i < F*32; i += blockDim.x) { sWk[i] = Wk[i]; sWv[i] = Wv[i]; }
    __syncthreads();
    int lane = threadIdx.x & 31;
    int gw = blockIdx.x * (blockDim.x >> 5) + (threadIdx.x >> 5);
    int n0 = gw * 4;
    if (n0 >= n) return;
    int m = n - n0; if (m > 4) m = 4;

    float4 xr[4];
#pragma unroll
    for (int j = 0; j < 4; j++) {
        if (j < m && lane * 4 < F)
            xr[j] = __ldg((const float4*)(x + (size_t)(n0 + j) * F) + lane);
        else
            xr[j] = make_float4(0.f, 0.f, 0.f, 0.f);
    }
    unsigned long long K01 = pack2(bk[lane], bk[lane]), K23 = K01;
    unsigned long long Q01 = pack2(bq[lane], bq[lane]), Q23 = Q01;
    unsigned long long V01 = pack2(bv[lane], bv[lane]), V23 = V01;

    for (int i0 = 0; i0 < F; i0 += 4) {
        int sl = i0 >> 2;
        float xs[4][4];
#pragma unroll
        for (int j = 0; j < 4; j++) {
            xs[j][0] = __shfl_sync(0xffffffffu, xr[j].x, sl);
            xs[j][1] = __shfl_sync(0xffffffffu, xr[j].y, sl);
            xs[j][2] = __shfl_sync(0xffffffffu, xr[j].z, sl);
            xs[j][3] = __shfl_sync(0xffffffffu, xr[j].w, sl);
        }
#pragma unroll
        for (int c = 0; c < 4; c++) {
            int i = i0 + c;
            float wq = __ldg(Wq + i * 32 + lane);
            float wk = sWk[i * 32 + lane];
            float wv = sWv[i * 32 + lane];
            unsigned long long wk2 = pack2(wk, wk), wq2 = pack2(wq, wq), wv2 = pack2(wv, wv);
            unsigned long long x01 = pack2(xs[0][c], xs[1][c]);
            unsigned long long x23 = pack2(xs[2][c], xs[3][c]);
            ffma2(K01, x01, wk2); ffma2(K23, x23, wk2);
            ffma2(Q01, x01, wq2); ffma2(Q23, x23, wq2);
            ffma2(V01, x01, wv2); ffma2(V23, x23, wv2);
        }
    }
    float2 k01 = unpack2(K01), k23 = unpack2(K23);
    float2 q01 = unpack2(Q01), q23 = unpack2(Q23);
    float2 v01 = unpack2(V01), v23 = unpack2(V23);
    float kk[4] = {k01.x, k01.y, k23.x, k23.y};
    float qq[4] = {q01.x, q01.y, q23.x, q23.y};
    float vv[4] = {v01.x, v01.y, v23.x, v23.y};
#pragma unroll
    for (int j = 0; j < 4; j++) {
        if (j < m) {
            size_t o = (size_t)(n0 + j) * 32 + lane;
            k[o] = kk[j]; q[o] = qq[j]; v[o] = vv[j];
        }
    }
}

template<int F>
__global__ void kqv2_kernel(const float* __restrict__ x,
                            const float* __restrict__ Wk, const float* __restrict__ bk,
                            const float* __restrict__ Wv, const float* __restrict__ bv,
                            float* __restrict__ k, float* __restrict__ v, int n) {
    __shared__ float sWk[F*32], sWv[F*32];
    for (int i = threadIdx.x; i < F*32; i += blockDim.x) { sWk[i] = Wk[i]; sWv[i] = Wv[i]; }
    __syncthreads();
    int lane = threadIdx.x & 31;
    int gw = blockIdx.x * (blockDim.x >> 5) + (threadIdx.x >> 5);
    int n0 = gw * 4;
    if (n0 >= n) return;
    int m = n - n0; if (m > 4) m = 4;

    float4 xr[4];
#pragma unroll
    for (int j = 0; j < 4; j++) {
        if (j < m && lane * 4 < F)
            xr[j] = __ldg((const float4*)(x + (size_t)(n0 + j) * F) + lane);
        else
            xr[j] = make_float4(0.f, 0.f, 0.f, 0.f);
    }
    unsigned long long K01 = pack2(bk[lane], bk[lane]), K23 = K01;
    unsigned long long V01 = pack2(bv[lane], bv[lane]), V23 = V01;

    for (int i0 = 0; i0 < F; i0 += 4) {
        int sl = i0 >> 2;
        float xs[4][4];
#pragma unroll
        for (int j = 0; j < 4; j++) {
            xs[j][0] = __shfl_sync(0xffffffffu, xr[j].x, sl);
            xs[j][1] = __shfl_sync(0xffffffffu, xr[j].y, sl);
            xs[j][2] = __shfl_sync(0xffffffffu, xr[j].z, sl);
            xs[j][3] = __shfl_sync(0xffffffffu, xr[j].w, sl);
        }
#pragma unroll
        for (int c = 0; c < 4; c++) {
            int i = i0 + c;
            float wk = sWk[i * 32 + lane];
            float wv = sWv[i * 32 + lane];
            unsigned long long wk2 = pack2(wk, wk), wv2 = pack2(wv, wv);
            unsigned long long x01 = pack2(xs[0][c], xs[1][c]);
            unsigned long long x23 = pack2(xs[2][c], xs[3][c]);
            ffma2(K01, x01, wk2); ffma2(K23, x23, wk2);
            ffma2(V01, x01, wv2); ffma2(V23, x23, wv2);
        }
    }
    float2 k01 = unpack2(K01), k23 = unpack2(K23);
    float2 v01 = unpack2(V01), v23 = unpack2(V23);
    float kk[4] = {k01.x, k01.y, k23.x, k23.y};
    float vv[4] = {v01.x, v01.y, v23.x, v23.y};
#pragma unroll
    for (int j = 0; j < 4; j++) {
        if (j < m) {
            size_t o = (size_t)(n0 + j) * 32 + lane;
            k[o] = kk[j]; v[o] = vv[j];
        }
    }
}

// ---------------- dst-centric edge aggregation (no atomics) -------------------
// 8 lanes per dst node, 4 dst per warp. q row + accumulators live in registers.
// Writes the NORMALIZED aggregate (x = sum(exp*v)/sum(exp)) directly.
__global__ void agg_kernel(const int* __restrict__ rp, const int* __restrict__ cs,
                           const float* __restrict__ q, const float* __restrict__ krel,
                           const float* __restrict__ vrel,
                           float* __restrict__ xout, int n) {
    int gw   = (blockIdx.x * blockDim.x + threadIdx.x) >> 5;
    int lane = threadIdx.x & 31;
    int sub  = lane >> 3;
    int ql   = lane & 7;
    unsigned gmask = 0xFFu << (sub * 8);
    int d = gw * 4 + sub;
    bool valid = (d < n);
    int dd = valid ? d : (n - 1);
    int b0 = __ldg(rp + dd);
    int b1 = __ldg(rp + dd + 1);
    if (!valid) b1 = b0;
    float4 qf = __ldg((const float4*)(q + (size_t)dd * 32) + ql);
    float ax = 0.f, ay = 0.f, az = 0.f, aw = 0.f, den = 0.f;
    int s = (b0 < b1) ? __ldg(cs + b0) : 0;
    for (int e = b0; e < b1; e++) {
        int sn = (e + 1 < b1) ? __ldg(cs + e + 1) : 0;
        float4 kf = __ldg((const float4*)(krel + (size_t)s * 32) + ql);
        float4 vf = __ldg((const float4*)(vrel + (size_t)s * 32) + ql);
        float sc = qf.x * kf.x + qf.y * kf.y + qf.z * kf.z + qf.w * kf.w;
        sc += __shfl_xor_sync(gmask, sc, 1);
        sc += __shfl_xor_sync(gmask, sc, 2);
        sc += __shfl_xor_sync(gmask, sc, 4);
        float ex = __expf(fminf(sc, 60.0f));
        ax = fmaf(ex, vf.x, ax);
        ay = fmaf(ex, vf.y, ay);
        az = fmaf(ex, vf.z, az);
        aw = fmaf(ex, vf.w, aw);
        den += ex;
        s = sn;
    }
    if (valid) {
        float inv = (den > 0.f) ? (1.0f / den) : 0.0f;
        float4 o = make_float4(ax * inv, ay * inv, az * inv, aw * inv);
        *((float4*)(xout + (size_t)d * 32) + ql) = o;
    }
}

// ---------------- output transform ---------------------------------------------
// o = gelu(x1 (+x2)) @ Wa + ba, optional gated skip. 4 nodes/warp, Wa in smem.
__global__ void out_kernel(const float* __restrict__ x1, const float* __restrict__ x2,
                           const float* __restrict__ Wa, const float* __restrict__ ba,
                           const float* __restrict__ skipv, int t_idx,
                           const float* __restrict__ xin,
                           float* __restrict__ out, int n, int use_skip) {
    __shared__ float sW[1024];
    for (int i = threadIdx.x; i < 1024; i += blockDim.x) sW[i] = Wa[i];
    __syncthreads();
    int lane = threadIdx.x & 31;
    int gw = blockIdx.x * (blockDim.x >> 5) + (threadIdx.x >> 5);
    int n0 = gw * 4;
    if (n0 >= n) return;
    int m = n - n0; if (m > 4) m = 4;

    float4 xr[4];
#pragma unroll
    for (int j = 0; j < 4; j++) {
        if (j < m && lane < 8) {
            float4 a = __ldg((const float4*)(x1 + (size_t)(n0 + j) * 32) + lane);
            if (x2) {
                float4 b2 = __ldg((const float4*)(x2 + (size_t)(n0 + j) * 32) + lane);
                a.x += b2.x; a.y += b2.y; a.z += b2.z; a.w += b2.w;
            }
            a.x = 0.5f * a.x * (1.0f + erff(a.x * 0.7071067811865475f));
            a.y = 0.5f * a.y * (1.0f + erff(a.y * 0.7071067811865475f));
            a.z = 0.5f * a.z * (1.0f + erff(a.z * 0.7071067811865475f));
            a.w = 0.5f * a.w * (1.0f + erff(a.w * 0.7071067811865475f));
            xr[j] = a;
        } else {
            xr[j] = make_float4(0.f, 0.f, 0.f, 0.f);
        }
    }
    unsigned long long A01 = pack2(ba[lane], ba[lane]), A23 = A01;
    for (int i0 = 0; i0 < 32; i0 += 4) {
        int sl = i0 >> 2;
        float xs[4][4];
#pragma unroll
        for (int j = 0; j < 4; j++) {
            xs[j][0] = __shfl_sync(0xffffffffu, xr[j].x, sl);
            xs[j][1] = __shfl_sync(0xffffffffu, xr[j].y, sl);
            xs[j][2] = __shfl_sync(0xffffffffu, xr[j].z, sl);
            xs[j][3] = __shfl_sync(0xffffffffu, xr[j].w, sl);
        }
#pragma unroll
        for (int c = 0; c < 4; c++) {
            float w = sW[(i0 + c) * 32 + lane];
            unsigned long long w2 = pack2(w, w);
            unsigned long long x01 = pack2(xs[0][c], xs[1][c]);
            unsigned long long x23 = pack2(xs[2][c], xs[3][c]);
            ffma2(A01, x01, w2); ffma2(A23, x23, w2);
        }
    }
    float2 a01 = unpack2(A01), a23 = unpack2(A23);
    float o[4] = {a01.x, a01.y, a23.x, a23.y};
    if (use_skip) {
        float a = 1.0f / (1.0f + expf(-__ldg(skipv + t_idx)));
#pragma unroll
        for (int j = 0; j < 4; j++) {
            if (j < m)
                o[j] = a * o[j] + (1.0f - a) * __ldg(xin + (size_t)(n0 + j) * 32 + lane);
        }
    }
#pragma unroll
    for (int j = 0; j < 4; j++) {
        if (j < m) out[(size_t)(n0 + j) * 32 + lane] = o[j];
    }
}

// ---------------- host orchestration ----------------------------------------

static void build_csr(const int* edges, int E, int n, int* deg, int* rp, int* cs, int* bsum) {
    const int BT = 256;
    int nb = divup(n, 1024);
    zero_int_kernel<<<divup(n, BT), BT>>>(deg, n);
    count_kernel<<<divup(E, BT), BT>>>(edges + E, E, deg);
    scan_p1<<<nb, 256>>>(deg, n, bsum);
    scan_p2<<<1, 256>>>(bsum, nb, rp + n);
    scan_p3<<<nb, 256>>>(deg, n, bsum, rp, deg);   // deg becomes cursor
    scatter_kernel<<<divup(E, BT), BT>>>(edges, edges + E, E, deg, cs);
}

static void run_layer(const float* xa, const float* xp, int F,
                      const float* Wk, const float* bk,
                      const float* Wq, const float* bq,
                      const float* Wv, const float* bv,
                      const float* Wa, const float* ba,
                      const float* skip, const float* arel, const float* mrel,
                      const float* prel, int use_skip,
                      float* outa, float* outp,
                      float* qa, float* qp,
                      float* k0, float* v0, float* k1, float* v1, float* k2, float* v2,
                      float* xa_agg, float* xpw, float* xpc,
                      const int* rp_w, const int* cs_w,
                      const int* rp_b, const int* cs_b,
                      const int* rp_c, const int* cs_c,
                      float* cW0, float* cb0, float* cW1, float* cb1,
                      float* cW2, float* cb2, float* cW3, float* cb3,
                      float* cW4, float* cb4, float* cW5, float* cb5) {
    const int BT = 256;
    int wsz = F * 32;
    int cgrid = divup((F + 1) * 32, BT);
    // composites: kA0 = Wk_a@arel0*s0, vA0 = Wv_a@mrel0, kP1/vP1, kP2/vP2
    compose_kernel<<<cgrid, BT>>>(Wk,       bk,      arel + 0*1024, prel, 0, cW0, cb0, F);
    compose_kernel<<<cgrid, BT>>>(Wv,       bv,      mrel + 0*1024, (const float*)0, 0, cW1, cb1, F);
    compose_kernel<<<cgrid, BT>>>(Wk + wsz, bk + 32, arel + 1*1024, prel, 1, cW2, cb2, F);
    compose_kernel<<<cgrid, BT>>>(Wv + wsz, bv + 32, mrel + 1*1024, (const float*)0, 0, cW3, cb3, F);
    compose_kernel<<<cgrid, BT>>>(Wk + wsz, bk + 32, arel + 2*1024, prel, 2, cW4, cb4, F);
    compose_kernel<<<cgrid, BT>>>(Wv + wsz, bv + 32, mrel + 2*1024, (const float*)0, 0, cW5, cb5, F);

    int ga = divup(divup(NA_, 4) * 32, BT);
    int gp = divup(divup(NP_, 4) * 32, BT);
    if (F == 128) {
        kqv3_kernel<128><<<ga, BT>>>(xa, Wq,       bq,      cW0, cb0, cW1, cb1, qa, k0, v0, NA_);
        kqv3_kernel<128><<<gp, BT>>>(xp, Wq + wsz, bq + 32, cW2, cb2, cW3, cb3, qp, k1, v1, NP_);
        kqv2_kernel<128><<<gp, BT>>>(xp, cW4, cb4, cW5, cb5, k2, v2, NP_);
    } else {
        kqv3_kernel<32><<<ga, BT>>>(xa, Wq,       bq,      cW0, cb0, cW1, cb1, qa, k0, v0, NA_);
        kqv3_kernel<32><<<gp, BT>>>(xp, Wq + wsz, bq + 32, cW2, cb2, cW3, cb3, qp, k1, v1, NP_);
        kqv2_kernel<32><<<gp, BT>>>(xp, cW4, cb4, cW5, cb5, k2, v2, NP_);
    }
    // edge aggregation (dst-centric, register accumulation)
    agg_kernel<<<gp, BT>>>(rp_w, cs_w, qp, k0, v0, xpw, NP_);   // writes: authors -> papers
    agg_kernel<<<ga, BT>>>(rp_b, cs_b, qa, k1, v1, xa_agg, NA_);// written_by: papers -> authors
    agg_kernel<<<gp, BT>>>(rp_c, cs_c, qp, k2, v2, xpc, NP_);   // cites: papers -> papers

    out_kernel<<<ga, BT>>>(xa_agg, (const float*)0, Wa,        ba,      skip, 0, xa, outa, NA_, use_skip);
    out_kernel<<<gp, BT>>>(xpw,    xpc,             Wa + 1024, ba + 32, skip, 1, xp, outp, NP_, use_skip);
}

extern "C" void kernel_launch(void* const* d_in, const int* in_sizes, int n_in,
                              void* d_out, int out_size) {
    const float* x_a   = (const float*)d_in[0];
    const float* x_p   = (const float*)d_in[1];
    const int* e_wr    = (const int*)d_in[2];
    const int* e_wb    = (const int*)d_in[3];
    const int* e_ci    = (const int*)d_in[4];
    const float* Wk1 = (const float*)d_in[5];  const float* bk1 = (const float*)d_in[6];
    const float* Wq1 = (const float*)d_in[7];  const float* bq1 = (const float*)d_in[8];
    const float* Wv1 = (const float*)d_in[9];  const float* bv1 = (const float*)d_in[10];
    const float* Wa1 = (const float*)d_in[11]; const float* ba1 = (const float*)d_in[12];
    const float* skip1 = (const float*)d_in[13];
    const float* arel1 = (const float*)d_in[14];
    const float* mrel1 = (const float*)d_in[15];
    const float* prel1 = (const float*)d_in[16];
    const float* Wk2 = (const float*)d_in[17]; const float* bk2 = (const float*)d_in[18];
    const float* Wq2 = (const float*)d_in[19]; const float* bq2 = (const float*)d_in[20];
    const float* Wv2 = (const float*)d_in[21]; const float* bv2 = (const float*)d_in[22];
    const float* Wa2 = (const float*)d_in[23]; const float* ba2 = (const float*)d_in[24];
    const float* skip2 = (const float*)d_in[25];
    const float* arel2 = (const float*)d_in[26];
    const float* mrel2 = (const float*)d_in[27];
    const float* prel2 = (const float*)d_in[28];

    float *qa,*qp,*k0,*v0,*k1,*v1,*k2,*v2,*xa_agg,*xpw,*xpc,*h1a,*h1p;
    cudaGetSymbolAddress((void**)&qa, g_qa);   cudaGetSymbolAddress((void**)&qp, g_qp);
    cudaGetSymbolAddress((void**)&k0, g_k0);   cudaGetSymbolAddress((void**)&v0, g_v0);
    cudaGetSymbolAddress((void**)&k1, g_k1);   cudaGetSymbolAddress((void**)&v1, g_v1);
    cudaGetSymbolAddress((void**)&k2, g_k2);   cudaGetSymbolAddress((void**)&v2, g_v2);
    cudaGetSymbolAddress((void**)&xa_agg, g_xa);
    cudaGetSymbolAddress((void**)&xpw, g_xpw); cudaGetSymbolAddress((void**)&xpc, g_xpc);
    cudaGetSymbolAddress((void**)&h1a, g_h1a); cudaGetSymbolAddress((void**)&h1p, g_h1p);

    int *deg_w,*rp_w,*cs_w,*deg_b,*rp_b,*cs_b,*deg_c,*rp_c,*cs_c,*bs_w,*bs_b,*bs_c;
    cudaGetSymbolAddress((void**)&deg_w, g_deg_w); cudaGetSymbolAddress((void**)&rp_w, g_rp_w);
    cudaGetSymbolAddress((void**)&cs_w, g_cs_w);
    cudaGetSymbolAddress((void**)&deg_b, g_deg_b); cudaGetSymbolAddress((void**)&rp_b, g_rp_b);
    cudaGetSymbolAddress((void**)&cs_b, g_cs_b);
    cudaGetSymbolAddress((void**)&deg_c, g_deg_c); cudaGetSymbolAddress((void**)&rp_c, g_rp_c);
    cudaGetSymbolAddress((void**)&cs_c, g_cs_c);
    cudaGetSymbolAddress((void**)&bs_w, g_bs_w);   cudaGetSymbolAddress((void**)&bs_b, g_bs_b);
    cudaGetSymbolAddress((void**)&bs_c, g_bs_c);

    float *cW[6], *cb[6];
    cudaGetSymbolAddress((void**)&cW[0], g_cW); cudaGetSymbolAddress((void**)&cb[0], g_cb);
    for (int i = 1; i < 6; i++) { cW[i] = cW[0] + i * 128 * 32; cb[i] = cb[0] + i * 32; }

    // CSR build (edges shared by both layers). Cites first: ncu slot 5 = scatter_c.
    build_csr(e_ci, EC_,  NP_, deg_c, rp_c, cs_c, bs_c);
    build_csr(e_wr, EW_,  NP_, deg_w, rp_w, cs_w, bs_w);
    build_csr(e_wb, EWB_, NA_, deg_b, rp_b, cs_b, bs_b);

    // Layer 1: 128 -> 32, no skip.
    run_layer(x_a, x_p, 128,
              Wk1, bk1, Wq1, bq1, Wv1, bv1, Wa1, ba1, skip1, arel1, mrel1, prel1, 0,
              h1a, h1p,
              qa, qp, k0, v0, k1, v1, k2, v2, xa_agg, xpw, xpc,
              rp_w, cs_w, rp_b, cs_b, rp_c, cs_c,
              cW[0], cb[0], cW[1], cb[1], cW[2], cb[2],
              cW[3], cb[3], cW[4], cb[4], cW[5], cb[5]);

    // Layer 2: 32 -> 32, gated skip.
    float* out = (float*)d_out;
    run_layer(h1a, h1p, 32,
              Wk2, bk2, Wq2, bq2, Wv2, bv2, Wa2, ba2, skip2, arel2, mrel2, prel2, 1,
              out, out + (size_t)NA_ * 32,
              qa, qp, k0, v0, k1, v1, k2, v2, xa_agg, xpw, xpc,
              rp_w, cs_w, rp_b, cs_b, rp_c, cs_c,
              cW[0], cb[0], cW[1], cb[1], cW[2], cb[2],
              cW[3], cb[3], cW[4], cb[4], cW[5], cb[5]);
}

// round 5
// speedup vs baseline: 1.7138x; 1.0576x over previous
#include <cuda_runtime.h>
#include <math.h>

#define NA_  100000
#define NP_  200000
#define EW_  1000000
#define EWB_ 1000000
#define EC_  2000000

// ---------------- scratch (device globals; no allocation allowed) ----------
__device__ float g_qa[NA_*32], g_qp[NP_*32];
__device__ float g_k0[NA_*32], g_v0[NA_*32];               // authors as src (rel 0)
__device__ float g_k1[NP_*32], g_v1[NP_*32];               // papers as src (rel 1)
__device__ float g_k2[NP_*32], g_v2[NP_*32];               // papers as src (rel 2)
__device__ float g_xa[NA_*32], g_xp[NP_*32];
__device__ float g_h1a[NA_*32], g_h1p[NP_*32];
// CSR per relation (dst-indexed)
__device__ int g_deg_w[NP_], g_rp_w[NP_+1];  __device__ int g_cs_w[EW_];
__device__ int g_deg_b[NA_], g_rp_b[NA_+1];  __device__ int g_cs_b[EWB_];
__device__ int g_deg_c[NP_], g_rp_c[NP_+1];  __device__ int g_cs_c[EC_];
__device__ int g_bs_w[256], g_bs_b[256], g_bs_c[256];
// composite weights: kA0,vA0,kP1,vP1,kP2,vP2 (max F=128) + biases
__device__ float g_cW[6][128*32];
__device__ float g_cb[6][32];

// ---------------- helpers ---------------------------------------------------
__device__ __forceinline__ unsigned long long pack2(float lo, float hi) {
    unsigned long long r;
    asm("mov.b64 %0, {%1,%2};" : "=l"(r) : "f"(lo), "f"(hi));
    return r;
}
__device__ __forceinline__ void ffma2(unsigned long long& acc,
                                      unsigned long long a, unsigned long long b) {
    asm("fma.rn.f32x2 %0, %1, %2, %0;" : "+l"(acc) : "l"(a), "l"(b));
}
__device__ __forceinline__ float2 unpack2(unsigned long long v) {
    float2 r;
    asm("mov.b64 {%0,%1}, %2;" : "=f"(r.x), "=f"(r.y) : "l"(v));
    return r;
}
static inline int divup(int a, int b) { return (a + b - 1) / b; }

// ---------------- CSR build --------------------------------------------------
__global__ void zero_int_kernel(int* __restrict__ p, int n) {
    int i = blockIdx.x * blockDim.x + threadIdx.x;
    if (i < n) p[i] = 0;
}
__global__ void count_kernel(const int* __restrict__ dst, int E, int* __restrict__ deg) {
    int e = blockIdx.x * blockDim.x + threadIdx.x;
    if (e < E) atomicAdd(&deg[dst[e]], 1);
}
__global__ void scan_p1(const int* __restrict__ deg, int n, int* __restrict__ bsum) {
    __shared__ int sm[256];
    int base = blockIdx.x * 1024;
    int t = threadIdx.x;
    int s = 0;
#pragma unroll
    for (int j = 0; j < 4; j++) {
        int i = base + t * 4 + j;
        if (i < n) s += deg[i];
    }
    sm[t] = s; __syncthreads();
#pragma unroll
    for (int o = 128; o > 0; o >>= 1) {
        if (t < o) sm[t] += sm[t + o];
        __syncthreads();
    }
    if (t == 0) bsum[blockIdx.x] = sm[0];
}
__global__ void scan_p2(int* __restrict__ bsum, int nb, int* __restrict__ rp_last) {
    __shared__ int sm[256];
    int t = threadIdx.x;
    int v = (t < nb) ? bsum[t] : 0;
    sm[t] = v; __syncthreads();
    for (int o = 1; o < 256; o <<= 1) {
        int x = (t >= o) ? sm[t - o] : 0;
        __syncthreads();
        sm[t] += x;
        __syncthreads();
    }
    if (t < nb) bsum[t] = sm[t] - v;   // exclusive
    if (t == 255) *rp_last = sm[255];  // total
}
__global__ void scan_p3(const int* __restrict__ deg, int n, const int* __restrict__ bsum,
                        int* __restrict__ rp, int* __restrict__ cur) {
    __shared__ int sm[256];
    int base = blockIdx.x * 1024;
    int t = threadIdx.x;
    int v[4]; int s = 0;
#pragma unroll
    for (int j = 0; j < 4; j++) {
        int i = base + t * 4 + j;
        v[j] = (i < n) ? deg[i] : 0;
        s += v[j];
    }
    sm[t] = s; __syncthreads();
    for (int o = 1; o < 256; o <<= 1) {
        int x = (t >= o) ? sm[t - o] : 0;
        __syncthreads();
        sm[t] += x;
        __syncthreads();
    }
    int run = bsum[blockIdx.x] + sm[t] - s;
#pragma unroll
    for (int j = 0; j < 4; j++) {
        int i = base + t * 4 + j;
        if (i < n) { rp[i] = run; cur[i] = run; }
        run += v[j];
    }
}
__global__ void scatter_kernel(const int* __restrict__ src, const int* __restrict__ dst,
                               int E, int* __restrict__ cur, int* __restrict__ cs) {
    int e = blockIdx.x * blockDim.x + threadIdx.x;
    if (e < E) {
        int slot = atomicAdd(&cur[dst[e]], 1);
        cs[slot] = src[e];
    }
}

// ---------------- weight composition -----------------------------------------
__global__ void compose_kernel(const float* __restrict__ W, const float* __restrict__ b,
                               const float* __restrict__ T, const float* __restrict__ prel,
                               int r, float* __restrict__ Wout, float* __restrict__ bout, int F) {
    int gw   = (blockIdx.x * blockDim.x + threadIdx.x) >> 5;
    int lane = threadIdx.x & 31;
    if (gw > F) return;
    float scale = prel ? (__ldg(prel + r) * 0.17677669529663687f) : 1.0f;
    const float* row = (gw < F) ? (W + (size_t)gw * 32) : b;
    float rv = row[lane];
    float acc = 0.f;
#pragma unroll
    for (int j = 0; j < 32; j++) {
        float rj = __shfl_sync(0xffffffffu, rv, j);
        acc = fmaf(rj, __ldg(T + j * 32 + lane), acc);
    }
    acc *= scale;
    if (gw < F) Wout[gw * 32 + lane] = acc;
    else        bout[lane] = acc;
}

// ---------------- projections -------------------------------------------------
// warp handles 8 nodes; lane = output dim. Wk/Wv transposed in smem (float4 LDS),
// Wq via LDG (L1). x preloaded as float4 + broadcast via shfl. f32x2 accumulation.
template<int F>
__global__ void kqv3_kernel(const float* __restrict__ x,
                            const float* __restrict__ Wq, const float* __restrict__ bq,
                            const float* __restrict__ Wk, const float* __restrict__ bk,
                            const float* __restrict__ Wv, const float* __restrict__ bv,
                            float* __restrict__ q, float* __restrict__ k, float* __restrict__ v,
                            int n) {
    const int S = F + 4;   // 16B-aligned, conflict-free stride
    __shared__ __align__(16) float sWk[32*(F+4)];
    __shared__ __align__(16) float sWv[32*(F+4)];
    for (int idx = threadIdx.x; idx < F*32; idx += blockDim.x) {
        int i = idx >> 5, l = idx & 31;
        sWk[l*S + i] = Wk[idx];
        sWv[l*S + i] = Wv[idx];
    }
    __syncthreads();
    int lane = threadIdx.x & 31;
    int gw = blockIdx.x * (blockDim.x >> 5) + (threadIdx.x >> 5);
    int n0 = gw * 8;
    if (n0 >= n) return;
    int m = n - n0; if (m > 8) m = 8;

    float4 xr[8];
#pragma unroll
    for (int j = 0; j < 8; j++)
        xr[j] = (j < m && lane * 4 < F)
              ? __ldg((const float4*)(x + (size_t)(n0 + j) * F) + lane)
              : make_float4(0.f, 0.f, 0.f, 0.f);

    unsigned long long Kp[4], Qp[4], Vp[4];
    {
        unsigned long long kb = pack2(bk[lane], bk[lane]);
        unsigned long long qb = pack2(bq[lane], bq[lane]);
        unsigned long long vb = pack2(bv[lane], bv[lane]);
#pragma unroll
        for (int p = 0; p < 4; p++) { Kp[p] = kb; Qp[p] = qb; Vp[p] = vb; }
    }

    for (int i0 = 0; i0 < F; i0 += 4) {
        int sl = i0 >> 2;
        float4 wk4 = *reinterpret_cast<const float4*>(&sWk[lane*S + i0]);
        float4 wv4 = *reinterpret_cast<const float4*>(&sWv[lane*S + i0]);
        float wq4[4];
#pragma unroll
        for (int c = 0; c < 4; c++) wq4[c] = __ldg(Wq + (i0 + c) * 32 + lane);
        float xs[8][4];
#pragma unroll
        for (int j = 0; j < 8; j++) {
            xs[j][0] = __shfl_sync(0xffffffffu, xr[j].x, sl);
            xs[j][1] = __shfl_sync(0xffffffffu, xr[j].y, sl);
            xs[j][2] = __shfl_sync(0xffffffffu, xr[j].z, sl);
            xs[j][3] = __shfl_sync(0xffffffffu, xr[j].w, sl);
        }
        float wkc[4] = {wk4.x, wk4.y, wk4.z, wk4.w};
        float wvc[4] = {wv4.x, wv4.y, wv4.z, wv4.w};
#pragma unroll
        for (int c = 0; c < 4; c++) {
            unsigned long long wk2 = pack2(wkc[c], wkc[c]);
            unsigned long long wq2 = pack2(wq4[c], wq4[c]);
            unsigned long long wv2 = pack2(wvc[c], wvc[c]);
#pragma unroll
            for (int p = 0; p < 4; p++) {
                unsigned long long xp = pack2(xs[2*p][c], xs[2*p+1][c]);
                ffma2(Kp[p], xp, wk2);
                ffma2(Qp[p], xp, wq2);
                ffma2(Vp[p], xp, wv2);
            }
        }
    }
#pragma unroll
    for (int p = 0; p < 4; p++) {
        float2 kf = unpack2(Kp[p]), qf = unpack2(Qp[p]), vf = unpack2(Vp[p]);
        int j0 = 2*p, j1 = 2*p + 1;
        if (j0 < m) { size_t o = (size_t)(n0 + j0)*32 + lane; k[o]=kf.x; q[o]=qf.x; v[o]=vf.x; }
        if (j1 < m) { size_t o = (size_t)(n0 + j1)*32 + lane; k[o]=kf.y; q[o]=qf.y; v[o]=vf.y; }
    }
}

template<int F>
__global__ void kqv2_kernel(const float* __restrict__ x,
                            const float* __restrict__ Wk, const float* __restrict__ bk,
                            const float* __restrict__ Wv, const float* __restrict__ bv,
                            float* __restrict__ k, float* __restrict__ v, int n) {
    const int S = F + 4;
    __shared__ __align__(16) float sWk[32*(F+4)];
    __shared__ __align__(16) float sWv[32*(F+4)];
    for (int idx = threadIdx.x; idx < F*32; idx += blockDim.x) {
        int i = idx >> 5, l = idx & 31;
        sWk[l*S + i] = Wk[idx];
        sWv[l*S + i] = Wv[idx];
    }
    __syncthreads();
    int lane = threadIdx.x & 31;
    int gw = blockIdx.x * (blockDim.x >> 5) + (threadIdx.x >> 5);
    int n0 = gw * 8;
    if (n0 >= n) return;
    int m = n - n0; if (m > 8) m = 8;

    float4 xr[8];
#pragma unroll
    for (int j = 0; j < 8; j++)
        xr[j] = (j < m && lane * 4 < F)
              ? __ldg((const float4*)(x + (size_t)(n0 + j) * F) + lane)
              : make_float4(0.f, 0.f, 0.f, 0.f);

    unsigned long long Kp[4], Vp[4];
    {
        unsigned long long kb = pack2(bk[lane], bk[lane]);
        unsigned long long vb = pack2(bv[lane], bv[lane]);
#pragma unroll
        for (int p = 0; p < 4; p++) { Kp[p] = kb; Vp[p] = vb; }
    }

    for (int i0 = 0; i0 < F; i0 += 4) {
        int sl = i0 >> 2;
        float4 wk4 = *reinterpret_cast<const float4*>(&sWk[lane*S + i0]);
        float4 wv4 = *reinterpret_cast<const float4*>(&sWv[lane*S + i0]);
        float xs[8][4];
#pragma unroll
        for (int j = 0; j < 8; j++) {
            xs[j][0] = __shfl_sync(0xffffffffu, xr[j].x, sl);
            xs[j][1] = __shfl_sync(0xffffffffu, xr[j].y, sl);
            xs[j][2] = __shfl_sync(0xffffffffu, xr[j].z, sl);
            xs[j][3] = __shfl_sync(0xffffffffu, xr[j].w, sl);
        }
        float wkc[4] = {wk4.x, wk4.y, wk4.z, wk4.w};
        float wvc[4] = {wv4.x, wv4.y, wv4.z, wv4.w};
#pragma unroll
        for (int c = 0; c < 4; c++) {
            unsigned long long wk2 = pack2(wkc[c], wkc[c]);
            unsigned long long wv2 = pack2(wvc[c], wvc[c]);
#pragma unroll
            for (int p = 0; p < 4; p++) {
                unsigned long long xp = pack2(xs[2*p][c], xs[2*p+1][c]);
                ffma2(Kp[p], xp, wk2);
                ffma2(Vp[p], xp, wv2);
            }
        }
    }
#pragma unroll
    for (int p = 0; p < 4; p++) {
        float2 kf = unpack2(Kp[p]), vf = unpack2(Vp[p]);
        int j0 = 2*p, j1 = 2*p + 1;
        if (j0 < m) { size_t o = (size_t)(n0 + j0)*32 + lane; k[o]=kf.x; v[o]=vf.x; }
        if (j1 < m) { size_t o = (size_t)(n0 + j1)*32 + lane; k[o]=kf.y; v[o]=vf.y; }
    }
}

// ---------------- dst-centric edge aggregation (no atomics) -------------------
// 8 lanes per dst node, 4 dst per warp. Unroll-by-2 over edges for MLP.
__device__ __forceinline__ float4 accum_rel(int b0, int b1, const int* __restrict__ cs,
                                            const float* __restrict__ kr,
                                            const float* __restrict__ vr,
                                            float4 qf, unsigned gmask, int ql) {
    float ax = 0.f, ay = 0.f, az = 0.f, aw = 0.f, den = 0.f;
    int e = b0;
    for (; e + 2 <= b1; e += 2) {
        int sA = __ldg(cs + e);
        int sB = __ldg(cs + e + 1);
        float4 kA = __ldg((const float4*)(kr + (size_t)sA * 32) + ql);
        float4 vA = __ldg((const float4*)(vr + (size_t)sA * 32) + ql);
        float4 kB = __ldg((const float4*)(kr + (size_t)sB * 32) + ql);
        float4 vB = __ldg((const float4*)(vr + (size_t)sB * 32) + ql);
        float scA = qf.x*kA.x + qf.y*kA.y + qf.z*kA.z + qf.w*kA.w;
        float scB = qf.x*kB.x + qf.y*kB.y + qf.z*kB.z + qf.w*kB.w;
        scA += __shfl_xor_sync(gmask, scA, 1);
        scB += __shfl_xor_sync(gmask, scB, 1);
        scA += __shfl_xor_sync(gmask, scA, 2);
        scB += __shfl_xor_sync(gmask, scB, 2);
        scA += __shfl_xor_sync(gmask, scA, 4);
        scB += __shfl_xor_sync(gmask, scB, 4);
        float exA = __expf(fminf(scA, 60.0f));
        float exB = __expf(fminf(scB, 60.0f));
        ax = fmaf(exA, vA.x, ax); ay = fmaf(exA, vA.y, ay);
        az = fmaf(exA, vA.z, az); aw = fmaf(exA, vA.w, aw);
        ax = fmaf(exB, vB.x, ax); ay = fmaf(exB, vB.y, ay);
        az = fmaf(exB, vB.z, az); aw = fmaf(exB, vB.w, aw);
        den += exA + exB;
    }
    if (e < b1) {
        int sA = __ldg(cs + e);
        float4 kA = __ldg((const float4*)(kr + (size_t)sA * 32) + ql);
        float4 vA = __ldg((const float4*)(vr + (size_t)sA * 32) + ql);
        float scA = qf.x*kA.x + qf.y*kA.y + qf.z*kA.z + qf.w*kA.w;
        scA += __shfl_xor_sync(gmask, scA, 1);
        scA += __shfl_xor_sync(gmask, scA, 2);
        scA += __shfl_xor_sync(gmask, scA, 4);
        float exA = __expf(fminf(scA, 60.0f));
        ax = fmaf(exA, vA.x, ax); ay = fmaf(exA, vA.y, ay);
        az = fmaf(exA, vA.z, az); aw = fmaf(exA, vA.w, aw);
        den += exA;
    }
    float inv = (den > 0.f) ? (1.0f / den) : 0.0f;
    return make_float4(ax * inv, ay * inv, az * inv, aw * inv);
}

// single-relation aggregation (authors)
__global__ void agg1_kernel(const int* __restrict__ rp, const int* __restrict__ cs,
                            const float* __restrict__ q, const float* __restrict__ kr,
                            const float* __restrict__ vr,
                            float* __restrict__ xout, int n) {
    int gw   = (blockIdx.x * blockDim.x + threadIdx.x) >> 5;
    int lane = threadIdx.x & 31;
    int sub  = lane >> 3;
    int ql   = lane & 7;
    unsigned gmask = 0xFFu << (sub * 8);
    int d = gw * 4 + sub;
    bool valid = (d < n);
    int dd = valid ? d : (n - 1);
    int b0 = __ldg(rp + dd);
    int b1 = valid ? __ldg(rp + dd + 1) : b0;
    float4 qf = __ldg((const float4*)(q + (size_t)dd * 32) + ql);
    float4 r = accum_rel(b0, b1, cs, kr, vr, qf, gmask, ql);
    if (valid) *((float4*)(xout + (size_t)d * 32) + ql) = r;
}

// two-relation fused aggregation (papers: writes + cites), writes summed x
__global__ void agg2_kernel(const int* __restrict__ rp1, const int* __restrict__ cs1,
                            const float* __restrict__ k1, const float* __restrict__ v1,
                            const int* __restrict__ rp2, const int* __restrict__ cs2,
                            const float* __restrict__ k2, const float* __restrict__ v2,
                            const float* __restrict__ q,
                            float* __restrict__ xout, int n) {
    int gw   = (blockIdx.x * blockDim.x + threadIdx.x) >> 5;
    int lane = threadIdx.x & 31;
    int sub  = lane >> 3;
    int ql   = lane & 7;
    unsigned gmask = 0xFFu << (sub * 8);
    int d = gw * 4 + sub;
    bool valid = (d < n);
    int dd = valid ? d : (n - 1);
    float4 qf = __ldg((const float4*)(q + (size_t)dd * 32) + ql);
    int a0 = __ldg(rp1 + dd);
    int a1 = valid ? __ldg(rp1 + dd + 1) : a0;
    int c0 = __ldg(rp2 + dd);
    int c1 = valid ? __ldg(rp2 + dd + 1) : c0;
    float4 r1 = accum_rel(a0, a1, cs1, k1, v1, qf, gmask, ql);
    float4 r2 = accum_rel(c0, c1, cs2, k2, v2, qf, gmask, ql);
    if (valid) {
        float4 o = make_float4(r1.x + r2.x, r1.y + r2.y, r1.z + r2.z, r1.w + r2.w);
        *((float4*)(xout + (size_t)d * 32) + ql) = o;
    }
}

// ---------------- output transform ---------------------------------------------
__global__ void out_kernel(const float* __restrict__ x1,
                           const float* __restrict__ Wa, const float* __restrict__ ba,
                           const float* __restrict__ skipv, int t_idx,
                           const float* __restrict__ xin,
                           float* __restrict__ out, int n, int use_skip) {
    __shared__ float sW[1024];
    for (int i = threadIdx.x; i < 1024; i += blockDim.x) sW[i] = Wa[i];
    __syncthreads();
    int lane = threadIdx.x & 31;
    int gw = blockIdx.x * (blockDim.x >> 5) + (threadIdx.x >> 5);
    int n0 = gw * 4;
    if (n0 >= n) return;
    int m = n - n0; if (m > 4) m = 4;

    float4 xr[4];
#pragma unroll
    for (int j = 0; j < 4; j++) {
        if (j < m && lane < 8) {
            float4 a = __ldg((const float4*)(x1 + (size_t)(n0 + j) * 32) + lane);
            a.x = 0.5f * a.x * (1.0f + erff(a.x * 0.7071067811865475f));
            a.y = 0.5f * a.y * (1.0f + erff(a.y * 0.7071067811865475f));
            a.z = 0.5f * a.z * (1.0f + erff(a.z * 0.7071067811865475f));
            a.w = 0.5f * a.w * (1.0f + erff(a.w * 0.7071067811865475f));
            xr[j] = a;
        } else {
            xr[j] = make_float4(0.f, 0.f, 0.f, 0.f);
        }
    }
    unsigned long long A01 = pack2(ba[lane], ba[lane]), A23 = A01;
    for (int i0 = 0; i0 < 32; i0 += 4) {
        int sl = i0 >> 2;
        float xs[4][4];
#pragma unroll
        for (int j = 0; j < 4; j++) {
            xs[j][0] = __shfl_sync(0xffffffffu, xr[j].x, sl);
            xs[j][1] = __shfl_sync(0xffffffffu, xr[j].y, sl);
            xs[j][2] = __shfl_sync(0xffffffffu, xr[j].z, sl);
            xs[j][3] = __shfl_sync(0xffffffffu, xr[j].w, sl);
        }
#pragma unroll
        for (int c = 0; c < 4; c++) {
            float w = sW[(i0 + c) * 32 + lane];
            unsigned long long w2 = pack2(w, w);
            unsigned long long x01 = pack2(xs[0][c], xs[1][c]);
            unsigned long long x23 = pack2(xs[2][c], xs[3][c]);
            ffma2(A01, x01, w2); ffma2(A23, x23, w2);
        }
    }
    float2 a01 = unpack2(A01), a23 = unpack2(A23);
    float o[4] = {a01.x, a01.y, a23.x, a23.y};
    if (use_skip) {
        float a = 1.0f / (1.0f + expf(-__ldg(skipv + t_idx)));
#pragma unroll
        for (int j = 0; j < 4; j++) {
            if (j < m)
                o[j] = a * o[j] + (1.0f - a) * __ldg(xin + (size_t)(n0 + j) * 32 + lane);
        }
    }
#pragma unroll
    for (int j = 0; j < 4; j++) {
        if (j < m) out[(size_t)(n0 + j) * 32 + lane] = o[j];
    }
}

// ---------------- host orchestration ----------------------------------------

static void build_csr(const int* edges, int E, int n, int* deg, int* rp, int* cs, int* bsum) {
    const int BT = 256;
    int nb = divup(n, 1024);
    zero_int_kernel<<<divup(n, BT), BT>>>(deg, n);
    count_kernel<<<divup(E, BT), BT>>>(edges + E, E, deg);
    scan_p1<<<nb, 256>>>(deg, n, bsum);
    scan_p2<<<1, 256>>>(bsum, nb, rp + n);
    scan_p3<<<nb, 256>>>(deg, n, bsum, rp, deg);   // deg becomes cursor
    scatter_kernel<<<divup(E, BT), BT>>>(edges, edges + E, E, deg, cs);
}

static void run_layer(const float* xa, const float* xp, int F,
                      const float* Wk, const float* bk,
                      const float* Wq, const float* bq,
                      const float* Wv, const float* bv,
                      const float* Wa, const float* ba,
                      const float* skip, const float* arel, const float* mrel,
                      const float* prel, int use_skip,
                      float* outa, float* outp,
                      float* qa, float* qp,
                      float* k0, float* v0, float* k1, float* v1, float* k2, float* v2,
                      float* xa_agg, float* xp_agg,
                      const int* rp_w, const int* cs_w,
                      const int* rp_b, const int* cs_b,
                      const int* rp_c, const int* cs_c,
                      float** cW, float** cb) {
    const int BT = 256;
    int wsz = F * 32;
    int cgrid = divup((F + 1) * 32, BT);
    compose_kernel<<<cgrid, BT>>>(Wk,       bk,      arel + 0*1024, prel, 0, cW[0], cb[0], F);
    compose_kernel<<<cgrid, BT>>>(Wv,       bv,      mrel + 0*1024, (const float*)0, 0, cW[1], cb[1], F);
    compose_kernel<<<cgrid, BT>>>(Wk + wsz, bk + 32, arel + 1*1024, prel, 1, cW[2], cb[2], F);
    compose_kernel<<<cgrid, BT>>>(Wv + wsz, bv + 32, mrel + 1*1024, (const float*)0, 0, cW[3], cb[3], F);
    compose_kernel<<<cgrid, BT>>>(Wk + wsz, bk + 32, arel + 2*1024, prel, 2, cW[4], cb[4], F);
    compose_kernel<<<cgrid, BT>>>(Wv + wsz, bv + 32, mrel + 2*1024, (const float*)0, 0, cW[5], cb[5], F);

    // 8 warps/block, 8 nodes/warp => 64 nodes per block
    int ga8 = divup(NA_, 64), gp8 = divup(NP_, 64);
    if (F == 128) {
        kqv3_kernel<128><<<ga8, BT>>>(xa, Wq,       bq,      cW[0], cb[0], cW[1], cb[1], qa, k0, v0, NA_);
        kqv3_kernel<128><<<gp8, BT>>>(xp, Wq + wsz, bq + 32, cW[2], cb[2], cW[3], cb[3], qp, k1, v1, NP_);
        kqv2_kernel<128><<<gp8, BT>>>(xp, cW[4], cb[4], cW[5], cb[5], k2, v2, NP_);
    } else {
        kqv3_kernel<32><<<ga8, BT>>>(xa, Wq,       bq,      cW[0], cb[0], cW[1], cb[1], qa, k0, v0, NA_);
        kqv3_kernel<32><<<gp8, BT>>>(xp, Wq + wsz, bq + 32, cW[2], cb[2], cW[3], cb[3], qp, k1, v1, NP_);
        kqv2_kernel<32><<<gp8, BT>>>(xp, cW[4], cb[4], cW[5], cb[5], k2, v2, NP_);
    }
    // edge aggregation (dst-centric, register accumulation)
    int ga4 = divup(divup(NA_, 4) * 32, BT);
    int gp4 = divup(divup(NP_, 4) * 32, BT);
    agg2_kernel<<<gp4, BT>>>(rp_w, cs_w, k0, v0, rp_c, cs_c, k2, v2, qp, xp_agg, NP_);
    agg1_kernel<<<ga4, BT>>>(rp_b, cs_b, qa, k1, v1, xa_agg, NA_);

    out_kernel<<<ga4, BT>>>(xa_agg, Wa,        ba,      skip, 0, xa, outa, NA_, use_skip);
    out_kernel<<<gp4, BT>>>(xp_agg, Wa + 1024, ba + 32, skip, 1, xp, outp, NP_, use_skip);
}

extern "C" void kernel_launch(void* const* d_in, const int* in_sizes, int n_in,
                              void* d_out, int out_size) {
    const float* x_a   = (const float*)d_in[0];
    const float* x_p   = (const float*)d_in[1];
    const int* e_wr    = (const int*)d_in[2];
    const int* e_wb    = (const int*)d_in[3];
    const int* e_ci    = (const int*)d_in[4];
    const float* Wk1 = (const float*)d_in[5];  const float* bk1 = (const float*)d_in[6];
    const float* Wq1 = (const float*)d_in[7];  const float* bq1 = (const float*)d_in[8];
    const float* Wv1 = (const float*)d_in[9];  const float* bv1 = (const float*)d_in[10];
    const float* Wa1 = (const float*)d_in[11]; const float* ba1 = (const float*)d_in[12];
    const float* skip1 = (const float*)d_in[13];
    const float* arel1 = (const float*)d_in[14];
    const float* mrel1 = (const float*)d_in[15];
    const float* prel1 = (const float*)d_in[16];
    const float* Wk2 = (const float*)d_in[17]; const float* bk2 = (const float*)d_in[18];
    const float* Wq2 = (const float*)d_in[19]; const float* bq2 = (const float*)d_in[20];
    const float* Wv2 = (const float*)d_in[21]; const float* bv2 = (const float*)d_in[22];
    const float* Wa2 = (const float*)d_in[23]; const float* ba2 = (const float*)d_in[24];
    const float* skip2 = (const float*)d_in[25];
    const float* arel2 = (const float*)d_in[26];
    const float* mrel2 = (const float*)d_in[27];
    const float* prel2 = (const float*)d_in[28];

    float *qa,*qp,*k0,*v0,*k1,*v1,*k2,*v2,*xa_agg,*xp_agg,*h1a,*h1p;
    cudaGetSymbolAddress((void**)&qa, g_qa);   cudaGetSymbolAddress((void**)&qp, g_qp);
    cudaGetSymbolAddress((void**)&k0, g_k0);   cudaGetSymbolAddress((void**)&v0, g_v0);
    cudaGetSymbolAddress((void**)&k1, g_k1);   cudaGetSymbolAddress((void**)&v1, g_v1);
    cudaGetSymbolAddress((void**)&k2, g_k2);   cudaGetSymbolAddress((void**)&v2, g_v2);
    cudaGetSymbolAddress((void**)&xa_agg, g_xa);
    cudaGetSymbolAddress((void**)&xp_agg, g_xp);
    cudaGetSymbolAddress((void**)&h1a, g_h1a); cudaGetSymbolAddress((void**)&h1p, g_h1p);

    int *deg_w,*rp_w,*cs_w,*deg_b,*rp_b,*cs_b,*deg_c,*rp_c,*cs_c,*bs_w,*bs_b,*bs_c;
    cudaGetSymbolAddress((void**)&deg_w, g_deg_w); cudaGetSymbolAddress((void**)&rp_w, g_rp_w);
    cudaGetSymbolAddress((void**)&cs_w, g_cs_w);
    cudaGetSymbolAddress((void**)&deg_b, g_deg_b); cudaGetSymbolAddress((void**)&rp_b, g_rp_b);
    cudaGetSymbolAddress((void**)&cs_b, g_cs_b);
    cudaGetSymbolAddress((void**)&deg_c, g_deg_c); cudaGetSymbolAddress((void**)&rp_c, g_rp_c);
    cudaGetSymbolAddress((void**)&cs_c, g_cs_c);
    cudaGetSymbolAddress((void**)&bs_w, g_bs_w);   cudaGetSymbolAddress((void**)&bs_b, g_bs_b);
    cudaGetSymbolAddress((void**)&bs_c, g_bs_c);

    float *cW[6], *cb[6];
    cudaGetSymbolAddress((void**)&cW[0], g_cW); cudaGetSymbolAddress((void**)&cb[0], g_cb);
    for (int i = 1; i < 6; i++) { cW[i] = cW[0] + i * 128 * 32; cb[i] = cb[0] + i * 32; }

    // CSR build (edges shared by both layers). Cites first: ncu slot 5 = scatter(cites).
    build_csr(e_ci, EC_,  NP_, deg_c, rp_c, cs_c, bs_c);
    build_csr(e_wr, EW_,  NP_, deg_w, rp_w, cs_w, bs_w);
    build_csr(e_wb, EWB_, NA_, deg_b, rp_b, cs_b, bs_b);

    // Layer 1: 128 -> 32, no skip.
    run_layer(x_a, x_p, 128,
              Wk1, bk1, Wq1, bq1, Wv1, bv1, Wa1, ba1, skip1, arel1, mrel1, prel1, 0,
              h1a, h1p,
              qa, qp, k0, v0, k1, v1, k2, v2, xa_agg, xp_agg,
              rp_w, cs_w, rp_b, cs_b, rp_c, cs_c, cW, cb);

    // Layer 2: 32 -> 32, gated skip.
    float* out = (float*)d_out;
    run_layer(h1a, h1p, 32,
              Wk2, bk2, Wq2, bq2, Wv2, bv2, Wa2, ba2, skip2, arel2, mrel2, prel2, 1,
              out, out + (size_t)NA_ * 32,
              qa, qp, k0, v0, k1, v1, k2, v2, xa_agg, xp_agg,
              rp_w, cs_w, rp_b, cs_b, rp_c, cs_c, cW, cb);
}

// round 6
// speedup vs baseline: 1.8049x; 1.0531x over previous
#include <cuda_runtime.h>
#include <cuda_fp16.h>
#include <math.h>

#define NA_  100000
#define NP_  200000
#define EW_  1000000
#define EWB_ 1000000
#define EC_  2000000

// ---------------- scratch (device globals; no allocation allowed) ----------
__device__ float g_qa[NA_*32], g_qp[NP_*32];
__device__ __align__(16) __half g_k0[NA_*32], g_v0[NA_*32];  // authors as src (rel 0)
__device__ __align__(16) __half g_k1[NP_*32], g_v1[NP_*32];  // papers as src (rel 1)
__device__ __align__(16) __half g_k2[NP_*32], g_v2[NP_*32];  // papers as src (rel 2)
__device__ float g_xa[NA_*32], g_xp[NP_*32];
__device__ float g_h1a[NA_*32], g_h1p[NP_*32];
// CSR per relation (dst-indexed)
__device__ int g_deg_w[NP_], g_rp_w[NP_+1];  __device__ int g_cs_w[EW_];
__device__ int g_deg_b[NA_], g_rp_b[NA_+1];  __device__ int g_cs_b[EWB_];
__device__ int g_deg_c[NP_], g_rp_c[NP_+1];  __device__ int g_cs_c[EC_];
__device__ int g_bs_w[256], g_bs_b[256], g_bs_c[256];
// composite weights: kA0,vA0,kP1,vP1,kP2,vP2 (max F=128) + biases
__device__ float g_cW[6][128*32];
__device__ float g_cb[6][32];

// ---------------- helpers ---------------------------------------------------
__device__ __forceinline__ unsigned long long pack2(float lo, float hi) {
    unsigned long long r;
    asm("mov.b64 %0, {%1,%2};" : "=l"(r) : "f"(lo), "f"(hi));
    return r;
}
__device__ __forceinline__ void ffma2(unsigned long long& acc,
                                      unsigned long long a, unsigned long long b) {
    asm("fma.rn.f32x2 %0, %1, %2, %0;" : "+l"(acc) : "l"(a), "l"(b));
}
__device__ __forceinline__ float2 unpack2(unsigned long long v) {
    float2 r;
    asm("mov.b64 {%0,%1}, %2;" : "=f"(r.x), "=f"(r.y) : "l"(v));
    return r;
}
static inline int divup(int a, int b) { return (a + b - 1) / b; }

// ---------------- CSR build --------------------------------------------------
__global__ void zero_int_kernel(int* __restrict__ p, int n) {
    int i = blockIdx.x * blockDim.x + threadIdx.x;
    if (i < n) p[i] = 0;
}
__global__ void count_kernel(const int* __restrict__ dst, int E, int* __restrict__ deg) {
    int e = blockIdx.x * blockDim.x + threadIdx.x;
    if (e < E) atomicAdd(&deg[dst[e]], 1);
}
__global__ void scan_p1(const int* __restrict__ deg, int n, int* __restrict__ bsum) {
    __shared__ int sm[256];
    int base = blockIdx.x * 1024;
    int t = threadIdx.x;
    int s = 0;
#pragma unroll
    for (int j = 0; j < 4; j++) {
        int i = base + t * 4 + j;
        if (i < n) s += deg[i];
    }
    sm[t] = s; __syncthreads();
#pragma unroll
    for (int o = 128; o > 0; o >>= 1) {
        if (t < o) sm[t] += sm[t + o];
        __syncthreads();
    }
    if (t == 0) bsum[blockIdx.x] = sm[0];
}
__global__ void scan_p2(int* __restrict__ bsum, int nb, int* __restrict__ rp_last) {
    __shared__ int sm[256];
    int t = threadIdx.x;
    int v = (t < nb) ? bsum[t] : 0;
    sm[t] = v; __syncthreads();
    for (int o = 1; o < 256; o <<= 1) {
        int x = (t >= o) ? sm[t - o] : 0;
        __syncthreads();
        sm[t] += x;
        __syncthreads();
    }
    if (t < nb) bsum[t] = sm[t] - v;   // exclusive
    if (t == 255) *rp_last = sm[255];  // total
}
__global__ void scan_p3(const int* __restrict__ deg, int n, const int* __restrict__ bsum,
                        int* __restrict__ rp, int* __restrict__ cur) {
    __shared__ int sm[256];
    int base = blockIdx.x * 1024;
    int t = threadIdx.x;
    int v[4]; int s = 0;
#pragma unroll
    for (int j = 0; j < 4; j++) {
        int i = base + t * 4 + j;
        v[j] = (i < n) ? deg[i] : 0;
        s += v[j];
    }
    sm[t] = s; __syncthreads();
    for (int o = 1; o < 256; o <<= 1) {
        int x = (t >= o) ? sm[t - o] : 0;
        __syncthreads();
        sm[t] += x;
        __syncthreads();
    }
    int run = bsum[blockIdx.x] + sm[t] - s;
#pragma unroll
    for (int j = 0; j < 4; j++) {
        int i = base + t * 4 + j;
        if (i < n) { rp[i] = run; cur[i] = run; }
        run += v[j];
    }
}
__global__ void scatter_kernel(const int* __restrict__ src, const int* __restrict__ dst,
                               int E, int* __restrict__ cur, int* __restrict__ cs) {
    int e = blockIdx.x * blockDim.x + threadIdx.x;
    if (e < E) {
        int slot = atomicAdd(&cur[dst[e]], 1);
        cs[slot] = src[e];
    }
}

// ---------------- weight composition -----------------------------------------
__global__ void compose_kernel(const float* __restrict__ W, const float* __restrict__ b,
                               const float* __restrict__ T, const float* __restrict__ prel,
                               int r, float* __restrict__ Wout, float* __restrict__ bout, int F) {
    int gw   = (blockIdx.x * blockDim.x + threadIdx.x) >> 5;
    int lane = threadIdx.x & 31;
    if (gw > F) return;
    float scale = prel ? (__ldg(prel + r) * 0.17677669529663687f) : 1.0f;
    const float* row = (gw < F) ? (W + (size_t)gw * 32) : b;
    float rv = row[lane];
    float acc = 0.f;
#pragma unroll
    for (int j = 0; j < 32; j++) {
        float rj = __shfl_sync(0xffffffffu, rv, j);
        acc = fmaf(rj, __ldg(T + j * 32 + lane), acc);
    }
    acc *= scale;
    if (gw < F) Wout[gw * 32 + lane] = acc;
    else        bout[lane] = acc;
}

// ---------------- projections -------------------------------------------------
// warp handles 8 nodes; lane = output dim. Wk/Wv transposed in smem (float4 LDS),
// Wq via LDG (L1). x preloaded as float4 + broadcast via shfl. f32x2 accumulation.
// q written fp32, k/v written fp16.
template<int F>
__global__ void kqv3_kernel(const float* __restrict__ x,
                            const float* __restrict__ Wq, const float* __restrict__ bq,
                            const float* __restrict__ Wk, const float* __restrict__ bk,
                            const float* __restrict__ Wv, const float* __restrict__ bv,
                            float* __restrict__ q, __half* __restrict__ k, __half* __restrict__ v,
                            int n) {
    const int S = F + 4;
    __shared__ __align__(16) float sWk[32*(F+4)];
    __shared__ __align__(16) float sWv[32*(F+4)];
    for (int idx = threadIdx.x; idx < F*32; idx += blockDim.x) {
        int i = idx >> 5, l = idx & 31;
        sWk[l*S + i] = Wk[idx];
        sWv[l*S + i] = Wv[idx];
    }
    __syncthreads();
    int lane = threadIdx.x & 31;
    int gw = blockIdx.x * (blockDim.x >> 5) + (threadIdx.x >> 5);
    int n0 = gw * 8;
    if (n0 >= n) return;
    int m = n - n0; if (m > 8) m = 8;

    float4 xr[8];
#pragma unroll
    for (int j = 0; j < 8; j++)
        xr[j] = (j < m && lane * 4 < F)
              ? __ldg((const float4*)(x + (size_t)(n0 + j) * F) + lane)
              : make_float4(0.f, 0.f, 0.f, 0.f);

    unsigned long long Kp[4], Qp[4], Vp[4];
    {
        unsigned long long kb = pack2(bk[lane], bk[lane]);
        unsigned long long qb = pack2(bq[lane], bq[lane]);
        unsigned long long vb = pack2(bv[lane], bv[lane]);
#pragma unroll
        for (int p = 0; p < 4; p++) { Kp[p] = kb; Qp[p] = qb; Vp[p] = vb; }
    }

    for (int i0 = 0; i0 < F; i0 += 4) {
        int sl = i0 >> 2;
        float4 wk4 = *reinterpret_cast<const float4*>(&sWk[lane*S + i0]);
        float4 wv4 = *reinterpret_cast<const float4*>(&sWv[lane*S + i0]);
        float wq4[4];
#pragma unroll
        for (int c = 0; c < 4; c++) wq4[c] = __ldg(Wq + (i0 + c) * 32 + lane);
        float xs[8][4];
#pragma unroll
        for (int j = 0; j < 8; j++) {
            xs[j][0] = __shfl_sync(0xffffffffu, xr[j].x, sl);
            xs[j][1] = __shfl_sync(0xffffffffu, xr[j].y, sl);
            xs[j][2] = __shfl_sync(0xffffffffu, xr[j].z, sl);
            xs[j][3] = __shfl_sync(0xffffffffu, xr[j].w, sl);
        }
        float wkc[4] = {wk4.x, wk4.y, wk4.z, wk4.w};
        float wvc[4] = {wv4.x, wv4.y, wv4.z, wv4.w};
#pragma unroll
        for (int c = 0; c < 4; c++) {
            unsigned long long wk2 = pack2(wkc[c], wkc[c]);
            unsigned long long wq2 = pack2(wq4[c], wq4[c]);
            unsigned long long wv2 = pack2(wvc[c], wvc[c]);
#pragma unroll
            for (int p = 0; p < 4; p++) {
                unsigned long long xp = pack2(xs[2*p][c], xs[2*p+1][c]);
                ffma2(Kp[p], xp, wk2);
                ffma2(Qp[p], xp, wq2);
                ffma2(Vp[p], xp, wv2);
            }
        }
    }
#pragma unroll
    for (int p = 0; p < 4; p++) {
        float2 kf = unpack2(Kp[p]), qf = unpack2(Qp[p]), vf = unpack2(Vp[p]);
        int j0 = 2*p, j1 = 2*p + 1;
        if (j0 < m) {
            size_t o = (size_t)(n0 + j0)*32 + lane;
            k[o] = __float2half(kf.x); q[o] = qf.x; v[o] = __float2half(vf.x);
        }
        if (j1 < m) {
            size_t o = (size_t)(n0 + j1)*32 + lane;
            k[o] = __float2half(kf.y); q[o] = qf.y; v[o] = __float2half(vf.y);
        }
    }
}

template<int F>
__global__ void kqv2_kernel(const float* __restrict__ x,
                            const float* __restrict__ Wk, const float* __restrict__ bk,
                            const float* __restrict__ Wv, const float* __restrict__ bv,
                            __half* __restrict__ k, __half* __restrict__ v, int n) {
    const int S = F + 4;
    __shared__ __align__(16) float sWk[32*(F+4)];
    __shared__ __align__(16) float sWv[32*(F+4)];
    for (int idx = threadIdx.x; idx < F*32; idx += blockDim.x) {
        int i = idx >> 5, l = idx & 31;
        sWk[l*S + i] = Wk[idx];
        sWv[l*S + i] = Wv[idx];
    }
    __syncthreads();
    int lane = threadIdx.x & 31;
    int gw = blockIdx.x * (blockDim.x >> 5) + (threadIdx.x >> 5);
    int n0 = gw * 8;
    if (n0 >= n) return;
    int m = n - n0; if (m > 8) m = 8;

    float4 xr[8];
#pragma unroll
    for (int j = 0; j < 8; j++)
        xr[j] = (j < m && lane * 4 < F)
              ? __ldg((const float4*)(x + (size_t)(n0 + j) * F) + lane)
              : make_float4(0.f, 0.f, 0.f, 0.f);

    unsigned long long Kp[4], Vp[4];
    {
        unsigned long long kb = pack2(bk[lane], bk[lane]);
        unsigned long long vb = pack2(bv[lane], bv[lane]);
#pragma unroll
        for (int p = 0; p < 4; p++) { Kp[p] = kb; Vp[p] = vb; }
    }

    for (int i0 = 0; i0 < F; i0 += 4) {
        int sl = i0 >> 2;
        float4 wk4 = *reinterpret_cast<const float4*>(&sWk[lane*S + i0]);
        float4 wv4 = *reinterpret_cast<const float4*>(&sWv[lane*S + i0]);
        float xs[8][4];
#pragma unroll
        for (int j = 0; j < 8; j++) {
            xs[j][0] = __shfl_sync(0xffffffffu, xr[j].x, sl);
            xs[j][1] = __shfl_sync(0xffffffffu, xr[j].y, sl);
            xs[j][2] = __shfl_sync(0xffffffffu, xr[j].z, sl);
            xs[j][3] = __shfl_sync(0xffffffffu, xr[j].w, sl);
        }
        float wkc[4] = {wk4.x, wk4.y, wk4.z, wk4.w};
        float wvc[4] = {wv4.x, wv4.y, wv4.z, wv4.w};
#pragma unroll
        for (int c = 0; c < 4; c++) {
            unsigned long long wk2 = pack2(wkc[c], wkc[c]);
            unsigned long long wv2 = pack2(wvc[c], wvc[c]);
#pragma unroll
            for (int p = 0; p < 4; p++) {
                unsigned long long xp = pack2(xs[2*p][c], xs[2*p+1][c]);
                ffma2(Kp[p], xp, wk2);
                ffma2(Vp[p], xp, wv2);
            }
        }
    }
#pragma unroll
    for (int p = 0; p < 4; p++) {
        float2 kf = unpack2(Kp[p]), vf = unpack2(Vp[p]);
        int j0 = 2*p, j1 = 2*p + 1;
        if (j0 < m) { size_t o = (size_t)(n0 + j0)*32 + lane; k[o]=__float2half(kf.x); v[o]=__float2half(vf.x); }
        if (j1 < m) { size_t o = (size_t)(n0 + j1)*32 + lane; k[o]=__float2half(kf.y); v[o]=__float2half(vf.y); }
    }
}

// ---------------- dst-centric edge aggregation (no atomics, fp16 k/v) ---------
// 4 lanes per dst node, 8 dst per warp. Unroll-by-2 over edges for MLP.
// fp32 q / score / accumulation; fp16 storage for gathered k/v.

__device__ __forceinline__ float edge_score(const uint4& kh, const float4& q0, const float4& q1) {
    float2 k0 = __half22float2(*(const __half2*)&kh.x);
    float2 k1 = __half22float2(*(const __half2*)&kh.y);
    float2 k2 = __half22float2(*(const __half2*)&kh.z);
    float2 k3 = __half22float2(*(const __half2*)&kh.w);
    float s = q0.x*k0.x + q0.y*k0.y + q0.z*k1.x + q0.w*k1.y
            + q1.x*k2.x + q1.y*k2.y + q1.z*k3.x + q1.w*k3.y;
    return s;
}
__device__ __forceinline__ void edge_accum(unsigned long long acc[4], const uint4& vh, float ex) {
    unsigned long long ex2 = pack2(ex, ex);
    float2 v0 = __half22float2(*(const __half2*)&vh.x);
    float2 v1 = __half22float2(*(const __half2*)&vh.y);
    float2 v2 = __half22float2(*(const __half2*)&vh.z);
    float2 v3 = __half22float2(*(const __half2*)&vh.w);
    ffma2(acc[0], pack2(v0.x, v0.y), ex2);
    ffma2(acc[1], pack2(v1.x, v1.y), ex2);
    ffma2(acc[2], pack2(v2.x, v2.y), ex2);
    ffma2(acc[3], pack2(v3.x, v3.y), ex2);
}

// accumulate one relation's edges into acc[4] (f32x2 pairs) and den; NOT normalized.
__device__ __forceinline__ float accum_rel_h(int b0, int b1, const int* __restrict__ cs,
                                             const __half* __restrict__ kr,
                                             const __half* __restrict__ vr,
                                             const float4& q0, const float4& q1,
                                             unsigned gmask, int ql,
                                             unsigned long long acc[4]) {
    float den = 0.f;
    int e = b0;
    for (; e + 2 <= b1; e += 2) {
        int sA = __ldg(cs + e);
        int sB = __ldg(cs + e + 1);
        uint4 kA = __ldg((const uint4*)(kr + (size_t)sA * 32) + ql);
        uint4 vA = __ldg((const uint4*)(vr + (size_t)sA * 32) + ql);
        uint4 kB = __ldg((const uint4*)(kr + (size_t)sB * 32) + ql);
        uint4 vB = __ldg((const uint4*)(vr + (size_t)sB * 32) + ql);
        float scA = edge_score(kA, q0, q1);
        float scB = edge_score(kB, q0, q1);
        scA += __shfl_xor_sync(gmask, scA, 1);
        scB += __shfl_xor_sync(gmask, scB, 1);
        scA += __shfl_xor_sync(gmask, scA, 2);
        scB += __shfl_xor_sync(gmask, scB, 2);
        float exA = __expf(fminf(scA, 60.0f));
        float exB = __expf(fminf(scB, 60.0f));
        edge_accum(acc, vA, exA);
        edge_accum(acc, vB, exB);
        den += exA + exB;
    }
    if (e < b1) {
        int sA = __ldg(cs + e);
        uint4 kA = __ldg((const uint4*)(kr + (size_t)sA * 32) + ql);
        uint4 vA = __ldg((const uint4*)(vr + (size_t)sA * 32) + ql);
        float scA = edge_score(kA, q0, q1);
        scA += __shfl_xor_sync(gmask, scA, 1);
        scA += __shfl_xor_sync(gmask, scA, 2);
        float exA = __expf(fminf(scA, 60.0f));
        edge_accum(acc, vA, exA);
        den += exA;
    }
    return den;
}

// single-relation aggregation (authors)
__global__ void agg1_kernel(const int* __restrict__ rp, const int* __restrict__ cs,
                            const float* __restrict__ q, const __half* __restrict__ kr,
                            const __half* __restrict__ vr,
                            float* __restrict__ xout, int n) {
    int gw   = (blockIdx.x * blockDim.x + threadIdx.x) >> 5;
    int lane = threadIdx.x & 31;
    int sub  = lane >> 2;   // group 0..7
    int ql   = lane & 3;    // quarter-row 0..3 (8 dims each)
    unsigned gmask = 0xFu << (sub * 4);
    int d = gw * 8 + sub;
    bool valid = (d < n);
    int dd = valid ? d : (n - 1);
    int b0 = __ldg(rp + dd);
    int b1 = valid ? __ldg(rp + dd + 1) : b0;
    float4 q0 = __ldg((const float4*)(q + (size_t)dd * 32) + ql * 2);
    float4 q1 = __ldg((const float4*)(q + (size_t)dd * 32) + ql * 2 + 1);
    unsigned long long acc[4];
    acc[0] = acc[1] = acc[2] = acc[3] = pack2(0.f, 0.f);
    float den = accum_rel_h(b0, b1, cs, kr, vr, q0, q1, gmask, ql, acc);
    if (valid) {
        float inv = (den > 0.f) ? (1.0f / den) : 0.0f;
        float2 a0 = unpack2(acc[0]), a1 = unpack2(acc[1]);
        float2 a2 = unpack2(acc[2]), a3 = unpack2(acc[3]);
        float4 o0 = make_float4(a0.x*inv, a0.y*inv, a1.x*inv, a1.y*inv);
        float4 o1 = make_float4(a2.x*inv, a2.y*inv, a3.x*inv, a3.y*inv);
        *((float4*)(xout + (size_t)d * 32) + ql * 2)     = o0;
        *((float4*)(xout + (size_t)d * 32) + ql * 2 + 1) = o1;
    }
}

// two-relation fused aggregation (papers: writes + cites), writes summed x
__global__ void agg2_kernel(const int* __restrict__ rp1, const int* __restrict__ cs1,
                            const __half* __restrict__ k1, const __half* __restrict__ v1,
                            const int* __restrict__ rp2, const int* __restrict__ cs2,
                            const __half* __restrict__ k2, const __half* __restrict__ v2,
                            const float* __restrict__ q,
                            float* __restrict__ xout, int n) {
    int gw   = (blockIdx.x * blockDim.x + threadIdx.x) >> 5;
    int lane = threadIdx.x & 31;
    int sub  = lane >> 2;
    int ql   = lane & 3;
    unsigned gmask = 0xFu << (sub * 4);
    int d = gw * 8 + sub;
    bool valid = (d < n);
    int dd = valid ? d : (n - 1);
    float4 q0 = __ldg((const float4*)(q + (size_t)dd * 32) + ql * 2);
    float4 q1 = __ldg((const float4*)(q + (size_t)dd * 32) + ql * 2 + 1);
    int a0 = __ldg(rp1 + dd);
    int a1 = valid ? __ldg(rp1 + dd + 1) : a0;
    int c0 = __ldg(rp2 + dd);
    int c1 = valid ? __ldg(rp2 + dd + 1) : c0;
    unsigned long long accA[4], accB[4];
    accA[0]=accA[1]=accA[2]=accA[3]=pack2(0.f,0.f);
    accB[0]=accB[1]=accB[2]=accB[3]=pack2(0.f,0.f);
    float denA = accum_rel_h(a0, a1, cs1, k1, v1, q0, q1, gmask, ql, accA);
    float denB = accum_rel_h(c0, c1, cs2, k2, v2, q0, q1, gmask, ql, accB);
    if (valid) {
        float invA = (denA > 0.f) ? (1.0f / denA) : 0.0f;
        float invB = (denB > 0.f) ? (1.0f / denB) : 0.0f;
        float2 rA[4], rB[4];
#pragma unroll
        for (int i = 0; i < 4; i++) { rA[i] = unpack2(accA[i]); rB[i] = unpack2(accB[i]); }
        float4 o0 = make_float4(rA[0].x*invA + rB[0].x*invB, rA[0].y*invA + rB[0].y*invB,
                                rA[1].x*invA + rB[1].x*invB, rA[1].y*invA + rB[1].y*invB);
        float4 o1 = make_float4(rA[2].x*invA + rB[2].x*invB, rA[2].y*invA + rB[2].y*invB,
                                rA[3].x*invA + rB[3].x*invB, rA[3].y*invA + rB[3].y*invB);
        *((float4*)(xout + (size_t)d * 32) + ql * 2)     = o0;
        *((float4*)(xout + (size_t)d * 32) + ql * 2 + 1) = o1;
    }
}

// ---------------- output transform ---------------------------------------------
__global__ void out_kernel(const float* __restrict__ x1,
                           const float* __restrict__ Wa, const float* __restrict__ ba,
                           const float* __restrict__ skipv, int t_idx,
                           const float* __restrict__ xin,
                           float* __restrict__ out, int n, int use_skip) {
    __shared__ float sW[1024];
    for (int i = threadIdx.x; i < 1024; i += blockDim.x) sW[i] = Wa[i];
    __syncthreads();
    int lane = threadIdx.x & 31;
    int gw = blockIdx.x * (blockDim.x >> 5) + (threadIdx.x >> 5);
    int n0 = gw * 4;
    if (n0 >= n) return;
    int m = n - n0; if (m > 4) m = 4;

    float4 xr[4];
#pragma unroll
    for (int j = 0; j < 4; j++) {
        if (j < m && lane < 8) {
            float4 a = __ldg((const float4*)(x1 + (size_t)(n0 + j) * 32) + lane);
            a.x = 0.5f * a.x * (1.0f + erff(a.x * 0.7071067811865475f));
            a.y = 0.5f * a.y * (1.0f + erff(a.y * 0.7071067811865475f));
            a.z = 0.5f * a.z * (1.0f + erff(a.z * 0.7071067811865475f));
            a.w = 0.5f * a.w * (1.0f + erff(a.w * 0.7071067811865475f));
            xr[j] = a;
        } else {
            xr[j] = make_float4(0.f, 0.f, 0.f, 0.f);
        }
    }
    unsigned long long A01 = pack2(ba[lane], ba[lane]), A23 = A01;
    for (int i0 = 0; i0 < 32; i0 += 4) {
        int sl = i0 >> 2;
        float xs[4][4];
#pragma unroll
        for (int j = 0; j < 4; j++) {
            xs[j][0] = __shfl_sync(0xffffffffu, xr[j].x, sl);
            xs[j][1] = __shfl_sync(0xffffffffu, xr[j].y, sl);
            xs[j][2] = __shfl_sync(0xffffffffu, xr[j].z, sl);
            xs[j][3] = __shfl_sync(0xffffffffu, xr[j].w, sl);
        }
#pragma unroll
        for (int c = 0; c < 4; c++) {
            float w = sW[(i0 + c) * 32 + lane];
            unsigned long long w2 = pack2(w, w);
            unsigned long long x01 = pack2(xs[0][c], xs[1][c]);
            unsigned long long x23 = pack2(xs[2][c], xs[3][c]);
            ffma2(A01, x01, w2); ffma2(A23, x23, w2);
        }
    }
    float2 a01 = unpack2(A01), a23 = unpack2(A23);
    float o[4] = {a01.x, a01.y, a23.x, a23.y};
    if (use_skip) {
        float a = 1.0f / (1.0f + expf(-__ldg(skipv + t_idx)));
#pragma unroll
        for (int j = 0; j < 4; j++) {
            if (j < m)
                o[j] = a * o[j] + (1.0f - a) * __ldg(xin + (size_t)(n0 + j) * 32 + lane);
        }
    }
#pragma unroll
    for (int j = 0; j < 4; j++) {
        if (j < m) out[(size_t)(n0 + j) * 32 + lane] = o[j];
    }
}

// ---------------- host orchestration ----------------------------------------

static void build_csr(const int* edges, int E, int n, int* deg, int* rp, int* cs, int* bsum) {
    const int BT = 256;
    int nb = divup(n, 1024);
    zero_int_kernel<<<divup(n, BT), BT>>>(deg, n);
    count_kernel<<<divup(E, BT), BT>>>(edges + E, E, deg);
    scan_p1<<<nb, 256>>>(deg, n, bsum);
    scan_p2<<<1, 256>>>(bsum, nb, rp + n);
    scan_p3<<<nb, 256>>>(deg, n, bsum, rp, deg);   // deg becomes cursor
    scatter_kernel<<<divup(E, BT), BT>>>(edges, edges + E, E, deg, cs);
}

static void run_layer(const float* xa, const float* xp, int F,
                      const float* Wk, const float* bk,
                      const float* Wq, const float* bq,
                      const float* Wv, const float* bv,
                      const float* Wa, const float* ba,
                      const float* skip, const float* arel, const float* mrel,
                      const float* prel, int use_skip,
                      float* outa, float* outp,
                      float* qa, float* qp,
                      __half* k0, __half* v0, __half* k1, __half* v1, __half* k2, __half* v2,
                      float* xa_agg, float* xp_agg,
                      const int* rp_w, const int* cs_w,
                      const int* rp_b, const int* cs_b,
                      const int* rp_c, const int* cs_c,
                      float** cW, float** cb) {
    const int BT = 256;
    int wsz = F * 32;
    int cgrid = divup((F + 1) * 32, BT);
    compose_kernel<<<cgrid, BT>>>(Wk,       bk,      arel + 0*1024, prel, 0, cW[0], cb[0], F);
    compose_kernel<<<cgrid, BT>>>(Wv,       bv,      mrel + 0*1024, (const float*)0, 0, cW[1], cb[1], F);
    compose_kernel<<<cgrid, BT>>>(Wk + wsz, bk + 32, arel + 1*1024, prel, 1, cW[2], cb[2], F);
    compose_kernel<<<cgrid, BT>>>(Wv + wsz, bv + 32, mrel + 1*1024, (const float*)0, 0, cW[3], cb[3], F);
    compose_kernel<<<cgrid, BT>>>(Wk + wsz, bk + 32, arel + 2*1024, prel, 2, cW[4], cb[4], F);
    compose_kernel<<<cgrid, BT>>>(Wv + wsz, bv + 32, mrel + 2*1024, (const float*)0, 0, cW[5], cb[5], F);

    int ga8 = divup(NA_, 64), gp8 = divup(NP_, 64);
    if (F == 128) {
        kqv3_kernel<128><<<ga8, BT>>>(xa, Wq,       bq,      cW[0], cb[0], cW[1], cb[1], qa, k0, v0, NA_);
        kqv3_kernel<128><<<gp8, BT>>>(xp, Wq + wsz, bq + 32, cW[2], cb[2], cW[3], cb[3], qp, k1, v1, NP_);
        kqv2_kernel<128><<<gp8, BT>>>(xp, cW[4], cb[4], cW[5], cb[5], k2, v2, NP_);
    } else {
        kqv3_kernel<32><<<ga8, BT>>>(xa, Wq,       bq,      cW[0], cb[0], cW[1], cb[1], qa, k0, v0, NA_);
        kqv3_kernel<32><<<gp8, BT>>>(xp, Wq + wsz, bq + 32, cW[2], cb[2], cW[3], cb[3], qp, k1, v1, NP_);
        kqv2_kernel<32><<<gp8, BT>>>(xp, cW[4], cb[4], cW[5], cb[5], k2, v2, NP_);
    }
    // edge aggregation: 8 dst/warp => 64 dst per 256-thread block
    int gaA = divup(NA_, 64), gpA = divup(NP_, 64);
    agg2_kernel<<<gpA, BT>>>(rp_w, cs_w, k0, v0, rp_c, cs_c, k2, v2, qp, xp_agg, NP_);
    agg1_kernel<<<gaA, BT>>>(rp_b, cs_b, qa, k1, v1, xa_agg, NA_);

    int ga4 = divup(divup(NA_, 4) * 32, BT);
    int gp4 = divup(divup(NP_, 4) * 32, BT);
    out_kernel<<<ga4, BT>>>(xa_agg, Wa,        ba,      skip, 0, xa, outa, NA_, use_skip);
    out_kernel<<<gp4, BT>>>(xp_agg, Wa + 1024, ba + 32, skip, 1, xp, outp, NP_, use_skip);
}

extern "C" void kernel_launch(void* const* d_in, const int* in_sizes, int n_in,
                              void* d_out, int out_size) {
    const float* x_a   = (const float*)d_in[0];
    const float* x_p   = (const float*)d_in[1];
    const int* e_wr    = (const int*)d_in[2];
    const int* e_wb    = (const int*)d_in[3];
    const int* e_ci    = (const int*)d_in[4];
    const float* Wk1 = (const float*)d_in[5];  const float* bk1 = (const float*)d_in[6];
    const float* Wq1 = (const float*)d_in[7];  const float* bq1 = (const float*)d_in[8];
    const float* Wv1 = (const float*)d_in[9];  const float* bv1 = (const float*)d_in[10];
    const float* Wa1 = (const float*)d_in[11]; const float* ba1 = (const float*)d_in[12];
    const float* skip1 = (const float*)d_in[13];
    const float* arel1 = (const float*)d_in[14];
    const float* mrel1 = (const float*)d_in[15];
    const float* prel1 = (const float*)d_in[16];
    const float* Wk2 = (const float*)d_in[17]; const float* bk2 = (const float*)d_in[18];
    const float* Wq2 = (const float*)d_in[19]; const float* bq2 = (const float*)d_in[20];
    const float* Wv2 = (const float*)d_in[21]; const float* bv2 = (const float*)d_in[22];
    const float* Wa2 = (const float*)d_in[23]; const float* ba2 = (const float*)d_in[24];
    const float* skip2 = (const float*)d_in[25];
    const float* arel2 = (const float*)d_in[26];
    const float* mrel2 = (const float*)d_in[27];
    const float* prel2 = (const float*)d_in[28];

    float *qa,*qp,*xa_agg,*xp_agg,*h1a,*h1p;
    __half *k0,*v0,*k1,*v1,*k2,*v2;
    cudaGetSymbolAddress((void**)&qa, g_qa);   cudaGetSymbolAddress((void**)&qp, g_qp);
    cudaGetSymbolAddress((void**)&k0, g_k0);   cudaGetSymbolAddress((void**)&v0, g_v0);
    cudaGetSymbolAddress((void**)&k1, g_k1);   cudaGetSymbolAddress((void**)&v1, g_v1);
    cudaGetSymbolAddress((void**)&k2, g_k2);   cudaGetSymbolAddress((void**)&v2, g_v2);
    cudaGetSymbolAddress((void**)&xa_agg, g_xa);
    cudaGetSymbolAddress((void**)&xp_agg, g_xp);
    cudaGetSymbolAddress((void**)&h1a, g_h1a); cudaGetSymbolAddress((void**)&h1p, g_h1p);

    int *deg_w,*rp_w,*cs_w,*deg_b,*rp_b,*cs_b,*deg_c,*rp_c,*cs_c,*bs_w,*bs_b,*bs_c;
    cudaGetSymbolAddress((void**)&deg_w, g_deg_w); cudaGetSymbolAddress((void**)&rp_w, g_rp_w);
    cudaGetSymbolAddress((void**)&cs_w, g_cs_w);
    cudaGetSymbolAddress((void**)&deg_b, g_deg_b); cudaGetSymbolAddress((void**)&rp_b, g_rp_b);
    cudaGetSymbolAddress((void**)&cs_b, g_cs_b);
    cudaGetSymbolAddress((void**)&deg_c, g_deg_c); cudaGetSymbolAddress((void**)&rp_c, g_rp_c);
    cudaGetSymbolAddress((void**)&cs_c, g_cs_c);
    cudaGetSymbolAddress((void**)&bs_w, g_bs_w);   cudaGetSymbolAddress((void**)&bs_b, g_bs_b);
    cudaGetSymbolAddress((void**)&bs_c, g_bs_c);

    float *cW[6], *cb[6];
    cudaGetSymbolAddress((void**)&cW[0], g_cW); cudaGetSymbolAddress((void**)&cb[0], g_cb);
    for (int i = 1; i < 6; i++) { cW[i] = cW[0] + i * 128 * 32; cb[i] = cb[0] + i * 32; }

    // CSR build (edges shared by both layers).
    build_csr(e_ci, EC_,  NP_, deg_c, rp_c, cs_c, bs_c);
    build_csr(e_wr, EW_,  NP_, deg_w, rp_w, cs_w, bs_w);
    build_csr(e_wb, EWB_, NA_, deg_b, rp_b, cs_b, bs_b);

    // Layer 1: 128 -> 32, no skip.
    run_layer(x_a, x_p, 128,
              Wk1, bk1, Wq1, bq1, Wv1, bv1, Wa1, ba1, skip1, arel1, mrel1, prel1, 0,
              h1a, h1p,
              qa, qp, k0, v0, k1, v1, k2, v2, xa_agg, xp_agg,
              rp_w, cs_w, rp_b, cs_b, rp_c, cs_c, cW, cb);

    // Layer 2: 32 -> 32, gated skip.
    float* out = (float*)d_out;
    run_layer(h1a, h1p, 32,
              Wk2, bk2, Wq2, bq2, Wv2, bv2, Wa2, ba2, skip2, arel2, mrel2, prel2, 1,
              out, out + (size_t)NA_ * 32,
              qa, qp, k0, v0, k1, v1, k2, v2, xa_agg, xp_agg,
              rp_w, cs_w, rp_b, cs_b, rp_c, cs_c, cW, cb);
}

// round 8
// speedup vs baseline: 2.3585x; 1.3067x over previous
#include <cuda_runtime.h>
#include <cuda_fp16.h>
#include <mma.h>
#include <math.h>
#include <stdint.h>

#define NA_  100000
#define NP_  200000
#define EW_  1000000
#define EWB_ 1000000
#define EC_  2000000

// ---------------- scratch (device globals; no allocation allowed) ----------
__device__ float g_qa[NA_*32], g_qp[NP_*32];
__device__ __align__(16) __half g_k0[NA_*32], g_v0[NA_*32];  // authors as src (rel 0)
__device__ __align__(16) __half g_k1[NP_*32], g_v1[NP_*32];  // papers as src (rel 1)
__device__ __align__(16) __half g_k2[NP_*32], g_v2[NP_*32];  // papers as src (rel 2)
__device__ float g_xa[NA_*32], g_xp[NP_*32];
__device__ float g_h1a[NA_*32], g_h1p[NP_*32];
__device__ __align__(32) __half g_x16a[NA_*128], g_x16p[NP_*128];
// CSR per relation (dst-indexed)
__device__ int g_deg_w[NP_], g_rp_w[NP_+1];  __device__ int g_cs_w[EW_];
__device__ int g_deg_b[NA_], g_rp_b[NA_+1];  __device__ int g_cs_b[EWB_];
__device__ int g_deg_c[NP_], g_rp_c[NP_+1];  __device__ int g_cs_c[EC_];
__device__ int g_bs_w[256], g_bs_b[256], g_bs_c[256];
// composite weights: 8 tasks x [32][KP<=128] fp16 (col-major B) + fp32 biases
__device__ __align__(32) __half g_Wt[8*32*128];
__device__ float g_bsv[8*32];

// ---------------- helpers ---------------------------------------------------
__device__ __forceinline__ unsigned long long pack2(float lo, float hi) {
    unsigned long long r;
    asm("mov.b64 %0, {%1,%2};" : "=l"(r) : "f"(lo), "f"(hi));
    return r;
}
__device__ __forceinline__ void ffma2(unsigned long long& acc,
                                      unsigned long long a, unsigned long long b) {
    asm("fma.rn.f32x2 %0, %1, %2, %0;" : "+l"(acc) : "l"(a), "l"(b));
}
__device__ __forceinline__ float2 unpack2(unsigned long long v) {
    float2 r;
    asm("mov.b64 {%0,%1}, %2;" : "=f"(r.x), "=f"(r.y) : "l"(v));
    return r;
}
static inline int divup(int a, int b) { return (a + b - 1) / b; }

// ---------------- CSR build --------------------------------------------------
__global__ void zero_int_kernel(int* __restrict__ p, int n) {
    int i = blockIdx.x * blockDim.x + threadIdx.x;
    if (i < n) p[i] = 0;
}
__global__ void count_kernel(const int* __restrict__ dst, int E, int* __restrict__ deg) {
    int e = blockIdx.x * blockDim.x + threadIdx.x;
    if (e < E) atomicAdd(&deg[dst[e]], 1);
}
__global__ void scan_p1(const int* __restrict__ deg, int n, int* __restrict__ bsum) {
    __shared__ int sm[256];
    int base = blockIdx.x * 1024;
    int t = threadIdx.x;
    int s = 0;
#pragma unroll
    for (int j = 0; j < 4; j++) {
        int i = base + t * 4 + j;
        if (i < n) s += deg[i];
    }
    sm[t] = s; __syncthreads();
#pragma unroll
    for (int o = 128; o > 0; o >>= 1) {
        if (t < o) sm[t] += sm[t + o];
        __syncthreads();
    }
    if (t == 0) bsum[blockIdx.x] = sm[0];
}
__global__ void scan_p2(int* __restrict__ bsum, int nb, int* __restrict__ rp_last) {
    __shared__ int sm[256];
    int t = threadIdx.x;
    int v = (t < nb) ? bsum[t] : 0;
    sm[t] = v; __syncthreads();
    for (int o = 1; o < 256; o <<= 1) {
        int x = (t >= o) ? sm[t - o] : 0;
        __syncthreads();
        sm[t] += x;
        __syncthreads();
    }
    if (t < nb) bsum[t] = sm[t] - v;
    if (t == 255) *rp_last = sm[255];
}
__global__ void scan_p3(const int* __restrict__ deg, int n, const int* __restrict__ bsum,
                        int* __restrict__ rp, int* __restrict__ cur) {
    __shared__ int sm[256];
    int base = blockIdx.x * 1024;
    int t = threadIdx.x;
    int v[4]; int s = 0;
#pragma unroll
    for (int j = 0; j < 4; j++) {
        int i = base + t * 4 + j;
        v[j] = (i < n) ? deg[i] : 0;
        s += v[j];
    }
    sm[t] = s; __syncthreads();
    for (int o = 1; o < 256; o <<= 1) {
        int x = (t >= o) ? sm[t - o] : 0;
        __syncthreads();
        sm[t] += x;
        __syncthreads();
    }
    int run = bsum[blockIdx.x] + sm[t] - s;
#pragma unroll
    for (int j = 0; j < 4; j++) {
        int i = base + t * 4 + j;
        if (i < n) { rp[i] = run; cur[i] = run; }
        run += v[j];
    }
}
__global__ void scatter_kernel(const int* __restrict__ src, const int* __restrict__ dst,
                               int E, int* __restrict__ cur, int* __restrict__ cs) {
    int e = blockIdx.x * blockDim.x + threadIdx.x;
    if (e < E) {
        int slot = atomicAdd(&cur[dst[e]], 1);
        cs[slot] = src[e];
    }
}

// ---------------- weight composition (all 8 tasks, one launch) -----------------
struct CTask { const float* W; const float* b; const float* T; int prel_idx; };
struct CArgs { CTask t[8]; const float* prel; };

// gridDim.y = 8 tasks. Row gw in [0,KP]: gw<F = weight row (transformed, fp16,
// stored Wt[task][32][KP] = col-major B); F<=gw<KP = zero pad; gw==KP = fp32 bias.
__global__ void compose_all_kernel(CArgs args, int F, int KP,
                                   __half* __restrict__ Wt, float* __restrict__ bs) {
    int task = blockIdx.y;
    int gw   = (blockIdx.x * blockDim.x + threadIdx.x) >> 5;
    int lane = threadIdx.x & 31;
    if (gw > KP) return;
    CTask tk = args.t[task];
    float scale = (tk.prel_idx >= 0) ? (__ldg(args.prel + tk.prel_idx) * 0.17677669529663687f) : 1.0f;
    if (gw == KP) {
        float rv = tk.b[lane];
        float acc;
        if (tk.T) {
            acc = 0.f;
#pragma unroll
            for (int j = 0; j < 32; j++) {
                float rj = __shfl_sync(0xffffffffu, rv, j);
                acc = fmaf(rj, __ldg(tk.T + j * 32 + lane), acc);
            }
        } else acc = rv;
        bs[task * 32 + lane] = acc * scale;
    } else if (gw >= F) {
        Wt[((size_t)task * 32 + lane) * KP + gw] = __float2half(0.f);
    } else {
        float rv = tk.W[(size_t)gw * 32 + lane];
        float acc;
        if (tk.T) {
            acc = 0.f;
#pragma unroll
            for (int j = 0; j < 32; j++) {
                float rj = __shfl_sync(0xffffffffu, rv, j);
                acc = fmaf(rj, __ldg(tk.T + j * 32 + lane), acc);
            }
        } else acc = rv;
        Wt[((size_t)task * 32 + lane) * KP + gw] = __float2half(acc * scale);
    }
}

// ---------------- fp32 -> fp16 (padded) conversion -----------------------------
__global__ void cvt16_kernel(const float* __restrict__ x, __half* __restrict__ y,
                             int n, int F, int KP) {
    int i = blockIdx.x * blockDim.x + threadIdx.x;
    int cpr = KP >> 2;
    int total = n * cpr;
    if (i >= total) return;
    int node = i / cpr;
    int c4 = (i % cpr) << 2;
    float4 v = (c4 < F) ? __ldg((const float4*)(x + (size_t)node * F + c4))
                        : make_float4(0.f, 0.f, 0.f, 0.f);
    __half2 h0 = __floats2half2_rn(v.x, v.y);
    __half2 h1 = __floats2half2_rn(v.z, v.w);
    __half2* dst = (__half2*)(y + (size_t)node * KP + c4);
    dst[0] = h0; dst[1] = h1;
}

// ---------------- wmma (HMMA) projection ---------------------------------------
// Block = 256 thr (8 warps) = 128 nodes; warp = 16-node m-tile. A = x tile fp16
// in smem (ld = KP+8). B = NMAT composite weights [32][KP] fp16 (col-major),
// loaded via L1. f32 accum; epilogue adds bias; mat0 -> fp32 q, rest -> fp16.
template<int KP, int NMAT>
__global__ void __launch_bounds__(256) proj_wmma_kernel(
        const __half* __restrict__ x16, const __half* __restrict__ Wt,
        const float* __restrict__ bias,
        float* __restrict__ qout,
        __half* __restrict__ o1, __half* __restrict__ o2,
        __half* __restrict__ o3, __half* __restrict__ o4, int n) {
    extern __shared__ __align__(32) char smem[];
    float* bsf   = (float*)smem;                               // NMAT*32 f32
    float* stage = (float*)(smem + NMAT * 32 * 4);             // 8 warps x 16x32 f32
    __half* sA   = (__half*)(smem + NMAT * 32 * 4 + 8 * 16 * 32 * 4);
    const int LDA = KP + 8;
    int tid = threadIdx.x, wid = tid >> 5, lane = tid & 31;
    int base = blockIdx.x * 128;

    if (tid < NMAT * 32) bsf[tid] = __ldg(bias + tid);
    const int CH = KP / 8;
    for (int idx = tid; idx < 128 * CH; idx += 256) {
        int row = idx / CH, c8 = (idx % CH) * 8;
        uint4 val = make_uint4(0, 0, 0, 0);
        if (base + row < n) val = *(const uint4*)(x16 + (size_t)(base + row) * KP + c8);
        *(uint4*)(sA + row * LDA + c8) = val;
    }
    __syncthreads();

    using namespace nvcuda;
    float* stW = stage + wid * 16 * 32;
    int m0 = wid * 16;
    __half* outs[4] = {o1, o2, o3, o4};
    int row = lane >> 1, c0 = (lane & 1) * 16;
    int node = base + m0 + row;
    bool store = (node < n);

#pragma unroll
    for (int mat = 0; mat < NMAT; mat++) {
        wmma::fragment<wmma::accumulator, 16, 16, 16, float> acc0, acc1;
        wmma::fill_fragment(acc0, 0.f);
        wmma::fill_fragment(acc1, 0.f);
        const __half* Wm = Wt + (size_t)mat * 32 * KP;
#pragma unroll
        for (int k0 = 0; k0 < KP; k0 += 16) {
            wmma::fragment<wmma::matrix_a, 16, 16, 16, __half, wmma::row_major> fa;
            wmma::fragment<wmma::matrix_b, 16, 16, 16, __half, wmma::col_major> fb0, fb1;
            wmma::load_matrix_sync(fa, sA + m0 * LDA + k0, LDA);
            wmma::load_matrix_sync(fb0, Wm + k0, KP);
            wmma::load_matrix_sync(fb1, Wm + 16 * KP + k0, KP);
            wmma::mma_sync(acc0, fa, fb0, acc0);
            wmma::mma_sync(acc1, fa, fb1, acc1);
        }
        wmma::store_matrix_sync(stW,      acc0, 32, wmma::mem_row_major);
        wmma::store_matrix_sync(stW + 16, acc1, 32, wmma::mem_row_major);
        __syncwarp();
        if (store) {
            if (mat == 0) {
                float4* dst = (float4*)(qout + (size_t)node * 32 + c0);
#pragma unroll
                for (int g = 0; g < 4; g++) {
                    float4 f;
                    f.x = stW[row * 32 + c0 + 4*g + 0] + bsf[c0 + 4*g + 0];
                    f.y = stW[row * 32 + c0 + 4*g + 1] + bsf[c0 + 4*g + 1];
                    f.z = stW[row * 32 + c0 + 4*g + 2] + bsf[c0 + 4*g + 2];
                    f.w = stW[row * 32 + c0 + 4*g + 3] + bsf[c0 + 4*g + 3];
                    dst[g] = f;
                }
            } else {
                uint32_t p[8];
#pragma unroll
                for (int c = 0; c < 8; c++) {
                    float lo = stW[row * 32 + c0 + 2*c]     + bsf[mat * 32 + c0 + 2*c];
                    float hi = stW[row * 32 + c0 + 2*c + 1] + bsf[mat * 32 + c0 + 2*c + 1];
                    __half2 h = __floats2half2_rn(lo, hi);
                    p[c] = *(uint32_t*)&h;
                }
                uint4* dst = (uint4*)(outs[mat - 1] + (size_t)node * 32 + c0);
                dst[0] = make_uint4(p[0], p[1], p[2], p[3]);
                dst[1] = make_uint4(p[4], p[5], p[6], p[7]);
            }
        }
        __syncwarp();
    }
}

// ---------------- dst-centric edge aggregation (no atomics, fp16 k/v) ---------
__device__ __forceinline__ float edge_score(const uint4& kh, const float4& q0, const float4& q1) {
    float2 k0 = __half22float2(*(const __half2*)&kh.x);
    float2 k1 = __half22float2(*(const __half2*)&kh.y);
    float2 k2 = __half22float2(*(const __half2*)&kh.z);
    float2 k3 = __half22float2(*(const __half2*)&kh.w);
    return q0.x*k0.x + q0.y*k0.y + q0.z*k1.x + q0.w*k1.y
         + q1.x*k2.x + q1.y*k2.y + q1.z*k3.x + q1.w*k3.y;
}
__device__ __forceinline__ void edge_accum(unsigned long long acc[4], const uint4& vh, float ex) {
    unsigned long long ex2 = pack2(ex, ex);
    float2 v0 = __half22float2(*(const __half2*)&vh.x);
    float2 v1 = __half22float2(*(const __half2*)&vh.y);
    float2 v2 = __half22float2(*(const __half2*)&vh.z);
    float2 v3 = __half22float2(*(const __half2*)&vh.w);
    ffma2(acc[0], pack2(v0.x, v0.y), ex2);
    ffma2(acc[1], pack2(v1.x, v1.y), ex2);
    ffma2(acc[2], pack2(v2.x, v2.y), ex2);
    ffma2(acc[3], pack2(v3.x, v3.y), ex2);
}
__device__ __forceinline__ float accum_rel_h(int b0, int b1, const int* __restrict__ cs,
                                             const __half* __restrict__ kr,
                                             const __half* __restrict__ vr,
                                             const float4& q0, const float4& q1,
                                             unsigned gmask, int ql,
                                             unsigned long long acc[4]) {
    float den = 0.f;
    int e = b0;
    for (; e + 2 <= b1; e += 2) {
        int sA = __ldg(cs + e);
        int sB = __ldg(cs + e + 1);
        uint4 kA = __ldg((const uint4*)(kr + (size_t)sA * 32) + ql);
        uint4 vA = __ldg((const uint4*)(vr + (size_t)sA * 32) + ql);
        uint4 kB = __ldg((const uint4*)(kr + (size_t)sB * 32) + ql);
        uint4 vB = __ldg((const uint4*)(vr + (size_t)sB * 32) + ql);
        float scA = edge_score(kA, q0, q1);
        float scB = edge_score(kB, q0, q1);
        scA += __shfl_xor_sync(gmask, scA, 1);
        scB += __shfl_xor_sync(gmask, scB, 1);
        scA += __shfl_xor_sync(gmask, scA, 2);
        scB += __shfl_xor_sync(gmask, scB, 2);
        float exA = __expf(fminf(scA, 60.0f));
        float exB = __expf(fminf(scB, 60.0f));
        edge_accum(acc, vA, exA);
        edge_accum(acc, vB, exB);
        den += exA + exB;
    }
    if (e < b1) {
        int sA = __ldg(cs + e);
        uint4 kA = __ldg((const uint4*)(kr + (size_t)sA * 32) + ql);
        uint4 vA = __ldg((const uint4*)(vr + (size_t)sA * 32) + ql);
        float scA = edge_score(kA, q0, q1);
        scA += __shfl_xor_sync(gmask, scA, 1);
        scA += __shfl_xor_sync(gmask, scA, 2);
        float exA = __expf(fminf(scA, 60.0f));
        edge_accum(acc, vA, exA);
        den += exA;
    }
    return den;
}
__global__ void agg1_kernel(const int* __restrict__ rp, const int* __restrict__ cs,
                            const float* __restrict__ q, const __half* __restrict__ kr,
                            const __half* __restrict__ vr,
                            float* __restrict__ xout, int n) {
    int gw   = (blockIdx.x * blockDim.x + threadIdx.x) >> 5;
    int lane = threadIdx.x & 31;
    int sub  = lane >> 2;
    int ql   = lane & 3;
    unsigned gmask = 0xFu << (sub * 4);
    int d = gw * 8 + sub;
    bool valid = (d < n);
    int dd = valid ? d : (n - 1);
    int b0 = __ldg(rp + dd);
    int b1 = valid ? __ldg(rp + dd + 1) : b0;
    float4 q0 = __ldg((const float4*)(q + (size_t)dd * 32) + ql * 2);
    float4 q1 = __ldg((const float4*)(q + (size_t)dd * 32) + ql * 2 + 1);
    unsigned long long acc[4];
    acc[0] = acc[1] = acc[2] = acc[3] = pack2(0.f, 0.f);
    float den = accum_rel_h(b0, b1, cs, kr, vr, q0, q1, gmask, ql, acc);
    if (valid) {
        float inv = (den > 0.f) ? (1.0f / den) : 0.0f;
        float2 a0 = unpack2(acc[0]), a1 = unpack2(acc[1]);
        float2 a2 = unpack2(acc[2]), a3 = unpack2(acc[3]);
        *((float4*)(xout + (size_t)d * 32) + ql * 2)     = make_float4(a0.x*inv, a0.y*inv, a1.x*inv, a1.y*inv);
        *((float4*)(xout + (size_t)d * 32) + ql * 2 + 1) = make_float4(a2.x*inv, a2.y*inv, a3.x*inv, a3.y*inv);
    }
}
__global__ void agg2_kernel(const int* __restrict__ rp1, const int* __restrict__ cs1,
                            const __half* __restrict__ k1, const __half* __restrict__ v1,
                            const int* __restrict__ rp2, const int* __restrict__ cs2,
                            const __half* __restrict__ k2, const __half* __restrict__ v2,
                            const float* __restrict__ q,
                            float* __restrict__ xout, int n) {
    int gw   = (blockIdx.x * blockDim.x + threadIdx.x) >> 5;
    int lane = threadIdx.x & 31;
    int sub  = lane >> 2;
    int ql   = lane & 3;
    unsigned gmask = 0xFu << (sub * 4);
    int d = gw * 8 + sub;
    bool valid = (d < n);
    int dd = valid ? d : (n - 1);
    float4 q0 = __ldg((const float4*)(q + (size_t)dd * 32) + ql * 2);
    float4 q1 = __ldg((const float4*)(q + (size_t)dd * 32) + ql * 2 + 1);
    int a0 = __ldg(rp1 + dd);
    int a1 = valid ? __ldg(rp1 + dd + 1) : a0;
    int c0 = __ldg(rp2 + dd);
    int c1 = valid ? __ldg(rp2 + dd + 1) : c0;
    unsigned long long accA[4], accB[4];
    accA[0]=accA[1]=accA[2]=accA[3]=pack2(0.f,0.f);
    accB[0]=accB[1]=accB[2]=accB[3]=pack2(0.f,0.f);
    float denA = accum_rel_h(a0, a1, cs1, k1, v1, q0, q1, gmask, ql, accA);
    float denB = accum_rel_h(c0, c1, cs2, k2, v2, q0, q1, gmask, ql, accB);
    if (valid) {
        float invA = (denA > 0.f) ? (1.0f / denA) : 0.0f;
        float invB = (denB > 0.f) ? (1.0f / denB) : 0.0f;
        float2 rA[4], rB[4];
#pragma unroll
        for (int i = 0; i < 4; i++) { rA[i] = unpack2(accA[i]); rB[i] = unpack2(accB[i]); }
        *((float4*)(xout + (size_t)d * 32) + ql * 2) =
            make_float4(rA[0].x*invA + rB[0].x*invB, rA[0].y*invA + rB[0].y*invB,
                        rA[1].x*invA + rB[1].x*invB, rA[1].y*invA + rB[1].y*invB);
        *((float4*)(xout + (size_t)d * 32) + ql * 2 + 1) =
            make_float4(rA[2].x*invA + rB[2].x*invB, rA[2].y*invA + rB[2].y*invB,
                        rA[3].x*invA + rB[3].x*invB, rA[3].y*invA + rB[3].y*invB);
    }
}

// ---------------- output transform ---------------------------------------------
__global__ void out_kernel(const float* __restrict__ x1,
                           const float* __restrict__ Wa, const float* __restrict__ ba,
                           const float* __restrict__ skipv, int t_idx,
                           const float* __restrict__ xin,
                           float* __restrict__ out, int n, int use_skip) {
    __shared__ float sW[1024];
    for (int i = threadIdx.x; i < 1024; i += blockDim.x) sW[i] = Wa[i];
    __syncthreads();
    int lane = threadIdx.x & 31;
    int gw = blockIdx.x * (blockDim.x >> 5) + (threadIdx.x >> 5);
    int n0 = gw * 4;
    if (n0 >= n) return;
    int m = n - n0; if (m > 4) m = 4;

    float4 xr[4];
#pragma unroll
    for (int j = 0; j < 4; j++) {
        if (j < m && lane < 8) {
            float4 a = __ldg((const float4*)(x1 + (size_t)(n0 + j) * 32) + lane);
            a.x = 0.5f * a.x * (1.0f + erff(a.x * 0.7071067811865475f));
            a.y = 0.5f * a.y * (1.0f + erff(a.y * 0.7071067811865475f));
            a.z = 0.5f * a.z * (1.0f + erff(a.z * 0.7071067811865475f));
            a.w = 0.5f * a.w * (1.0f + erff(a.w * 0.7071067811865475f));
            xr[j] = a;
        } else {
            xr[j] = make_float4(0.f, 0.f, 0.f, 0.f);
        }
    }
    unsigned long long A01 = pack2(ba[lane], ba[lane]), A23 = A01;
    for (int i0 = 0; i0 < 32; i0 += 4) {
        int sl = i0 >> 2;
        float xs[4][4];
#pragma unroll
        for (int j = 0; j < 4; j++) {
            xs[j][0] = __shfl_sync(0xffffffffu, xr[j].x, sl);
            xs[j][1] = __shfl_sync(0xffffffffu, xr[j].y, sl);
            xs[j][2] = __shfl_sync(0xffffffffu, xr[j].z, sl);
            xs[j][3] = __shfl_sync(0xffffffffu, xr[j].w, sl);
        }
#pragma unroll
        for (int c = 0; c < 4; c++) {
            float w = sW[(i0 + c) * 32 + lane];
            unsigned long long w2 = pack2(w, w);
            ffma2(A01, pack2(xs[0][c], xs[1][c]), w2);
            ffma2(A23, pack2(xs[2][c], xs[3][c]), w2);
        }
    }
    float2 a01 = unpack2(A01), a23 = unpack2(A23);
    float o[4] = {a01.x, a01.y, a23.x, a23.y};
    if (use_skip) {
        float a = 1.0f / (1.0f + expf(-__ldg(skipv + t_idx)));
#pragma unroll
        for (int j = 0; j < 4; j++) {
            if (j < m)
                o[j] = a * o[j] + (1.0f - a) * __ldg(xin + (size_t)(n0 + j) * 32 + lane);
        }
    }
#pragma unroll
    for (int j = 0; j < 4; j++) {
        if (j < m) out[(size_t)(n0 + j) * 32 + lane] = o[j];
    }
}

// ---------------- host orchestration ----------------------------------------
static void build_csr(const int* edges, int E, int n, int* deg, int* rp, int* cs, int* bsum) {
    const int BT = 256;
    int nb = divup(n, 1024);
    zero_int_kernel<<<divup(n, BT), BT>>>(deg, n);
    count_kernel<<<divup(E, BT), BT>>>(edges + E, E, deg);
    scan_p1<<<nb, 256>>>(deg, n, bsum);
    scan_p2<<<1, 256>>>(bsum, nb, rp + n);
    scan_p3<<<nb, 256>>>(deg, n, bsum, rp, deg);
    scatter_kernel<<<divup(E, BT), BT>>>(edges, edges + E, E, deg, cs);
}

struct LayerW {
    const float *Wk, *bk, *Wq, *bq, *Wv, *bv, *Wa, *ba, *skip, *arel, *mrel, *prel;
};

template<int KP>
static void run_layer(const __half* x16a, const __half* x16p, int F,
                      const LayerW& L, int use_skip,
                      const float* xa_skip, const float* xp_skip,
                      float* outa, float* outp,
                      float* qa, float* qp,
                      __half* k0, __half* v0, __half* k1, __half* v1, __half* k2, __half* v2,
                      float* xa_agg, float* xp_agg,
                      const int* rp_w, const int* cs_w,
                      const int* rp_b, const int* cs_b,
                      const int* rp_c, const int* cs_c,
                      __half* Wt, float* bs) {
    const int BT = 256;
    int wsz = F * 32;
    CArgs ca;
    ca.prel = L.prel;
    ca.t[0] = { L.Wq,       L.bq,      (const float*)0, -1 };   // q authors
    ca.t[1] = { L.Wk,       L.bk,      L.arel + 0,      0  };   // k0
    ca.t[2] = { L.Wv,       L.bv,      L.mrel + 0,      -1 };   // v0
    ca.t[3] = { L.Wq + wsz, L.bq + 32, (const float*)0, -1 };   // q papers
    ca.t[4] = { L.Wk + wsz, L.bk + 32, L.arel + 1024,   1  };   // k1
    ca.t[5] = { L.Wv + wsz, L.bv + 32, L.mrel + 1024,   -1 };   // v1
    ca.t[6] = { L.Wk + wsz, L.bk + 32, L.arel + 2048,   2  };   // k2
    ca.t[7] = { L.Wv + wsz, L.bv + 32, L.mrel + 2048,   -1 };   // v2
    dim3 cg(divup((KP + 1) * 32, BT), 8);
    compose_all_kernel<<<cg, BT>>>(ca, F, KP, Wt, bs);

    int smem_a = 3 * 32 * 4 + 8 * 16 * 32 * 4 + 128 * (KP + 8) * 2;
    int smem_p = 5 * 32 * 4 + 8 * 16 * 32 * 4 + 128 * (KP + 8) * 2;
    proj_wmma_kernel<KP, 3><<<divup(NA_, 128), 256, smem_a>>>(
        x16a, Wt, bs, qa, k0, v0, (__half*)0, (__half*)0, NA_);
    proj_wmma_kernel<KP, 5><<<divup(NP_, 128), 256, smem_p>>>(
        x16p, Wt + (size_t)3 * 32 * KP, bs + 3 * 32, qp, k1, v1, k2, v2, NP_);

    int gaA = divup(NA_, 64), gpA = divup(NP_, 64);
    agg2_kernel<<<gpA, BT>>>(rp_w, cs_w, k0, v0, rp_c, cs_c, k2, v2, qp, xp_agg, NP_);
    agg1_kernel<<<gaA, BT>>>(rp_b, cs_b, qa, k1, v1, xa_agg, NA_);

    int ga4 = divup(divup(NA_, 4) * 32, BT);
    int gp4 = divup(divup(NP_, 4) * 32, BT);
    out_kernel<<<ga4, BT>>>(xa_agg, L.Wa,        L.ba,      L.skip, 0, xa_skip, outa, NA_, use_skip);
    out_kernel<<<gp4, BT>>>(xp_agg, L.Wa + 1024, L.ba + 32, L.skip, 1, xp_skip, outp, NP_, use_skip);
}

extern "C" void kernel_launch(void* const* d_in, const int* in_sizes, int n_in,
                              void* d_out, int out_size) {
    const float* x_a   = (const float*)d_in[0];
    const float* x_p   = (const float*)d_in[1];
    const int* e_wr    = (const int*)d_in[2];
    const int* e_wb    = (const int*)d_in[3];
    const int* e_ci    = (const int*)d_in[4];
    LayerW L1 = { (const float*)d_in[5],  (const float*)d_in[6],
                  (const float*)d_in[7],  (const float*)d_in[8],
                  (const float*)d_in[9],  (const float*)d_in[10],
                  (const float*)d_in[11], (const float*)d_in[12],
                  (const float*)d_in[13], (const float*)d_in[14],
                  (const float*)d_in[15], (const float*)d_in[16] };
    LayerW L2 = { (const float*)d_in[17], (const float*)d_in[18],
                  (const float*)d_in[19], (const float*)d_in[20],
                  (const float*)d_in[21], (const float*)d_in[22],
                  (const float*)d_in[23], (const float*)d_in[24],
                  (const float*)d_in[25], (const float*)d_in[26],
                  (const float*)d_in[27], (const float*)d_in[28] };

    float *qa,*qp,*xa_agg,*xp_agg,*h1a,*h1p,*bs;
    __half *k0,*v0,*k1,*v1,*k2,*v2,*x16a,*x16p,*Wt;
    cudaGetSymbolAddress((void**)&qa, g_qa);   cudaGetSymbolAddress((void**)&qp, g_qp);
    cudaGetSymbolAddress((void**)&k0, g_k0);   cudaGetSymbolAddress((void**)&v0, g_v0);
    cudaGetSymbolAddress((void**)&k1, g_k1);   cudaGetSymbolAddress((void**)&v1, g_v1);
    cudaGetSymbolAddress((void**)&k2, g_k2);   cudaGetSymbolAddress((void**)&v2, g_v2);
    cudaGetSymbolAddress((void**)&xa_agg, g_xa);
    cudaGetSymbolAddress((void**)&xp_agg, g_xp);
    cudaGetSymbolAddress((void**)&h1a, g_h1a); cudaGetSymbolAddress((void**)&h1p, g_h1p);
    cudaGetSymbolAddress((void**)&x16a, g_x16a); cudaGetSymbolAddress((void**)&x16p, g_x16p);
    cudaGetSymbolAddress((void**)&Wt, g_Wt);   cudaGetSymbolAddress((void**)&bs, g_bsv);

    int *deg_w,*rp_w,*cs_w,*deg_b,*rp_b,*cs_b,*deg_c,*rp_c,*cs_c,*bs_w,*bs_b,*bs_c;
    cudaGetSymbolAddress((void**)&deg_w, g_deg_w); cudaGetSymbolAddress((void**)&rp_w, g_rp_w);
    cudaGetSymbolAddress((void**)&cs_w, g_cs_w);
    cudaGetSymbolAddress((void**)&deg_b, g_deg_b); cudaGetSymbolAddress((void**)&rp_b, g_rp_b);
    cudaGetSymbolAddress((void**)&cs_b, g_cs_b);
    cudaGetSymbolAddress((void**)&deg_c, g_deg_c); cudaGetSymbolAddress((void**)&rp_c, g_rp_c);
    cudaGetSymbolAddress((void**)&cs_c, g_cs_c);
    cudaGetSymbolAddress((void**)&bs_w, g_bs_w);   cudaGetSymbolAddress((void**)&bs_b, g_bs_b);
    cudaGetSymbolAddress((void**)&bs_c, g_bs_c);

    // opt-in for >48KB dynamic smem on layer-1 proj kernels (host attr, capture-safe)
    cudaFuncSetAttribute(proj_wmma_kernel<128,3>, cudaFuncAttributeMaxDynamicSharedMemorySize,
                         3*32*4 + 8*16*32*4 + 128*(128+8)*2);
    cudaFuncSetAttribute(proj_wmma_kernel<128,5>, cudaFuncAttributeMaxDynamicSharedMemorySize,
                         5*32*4 + 8*16*32*4 + 128*(128+8)*2);

    // CSR build (edges shared by both layers).
    build_csr(e_ci, EC_,  NP_, deg_c, rp_c, cs_c, bs_c);
    build_csr(e_wr, EW_,  NP_, deg_w, rp_w, cs_w, bs_w);
    build_csr(e_wb, EWB_, NA_, deg_b, rp_b, cs_b, bs_b);

    const int BT = 256;
    // Layer 1 inputs -> fp16 (KP = 128)
    cvt16_kernel<<<divup(NA_*32, BT), BT>>>(x_a, x16a, NA_, 128, 128);
    cvt16_kernel<<<divup(NP_*32, BT), BT>>>(x_p, x16p, NP_, 128, 128);
    run_layer<128>(x16a, x16p, 128, L1, 0, x_a, x_p, h1a, h1p,
                   qa, qp, k0, v0, k1, v1, k2, v2, xa_agg, xp_agg,
                   rp_w, cs_w, rp_b, cs_b, rp_c, cs_c, Wt, bs);

    // Layer 2 inputs -> fp16 (KP = 32)
    cvt16_kernel<<<divup(NA_*8, BT), BT>>>(h1a, x16a, NA_, 32, 32);
    cvt16_kernel<<<divup(NP_*8, BT), BT>>>(h1p, x16p, NP_, 32, 32);
    float* out = (float*)d_out;
    run_layer<32>(x16a, x16p, 32, L2, 1, h1a, h1p, out, out + (size_t)NA_ * 32,
                  qa, qp, k0, v0, k1, v1, k2, v2, xa_agg, xp_agg,
                  rp_w, cs_w, rp_b, cs_b, rp_c, cs_c, Wt, bs);
}

// round 9
// speedup vs baseline: 2.3596x; 1.0005x over previous
#include <cuda_runtime.h>
#include <cuda_fp16.h>
#include <mma.h>
#include <math.h>
#include <stdint.h>

#define NA_  100000
#define NP_  200000
#define EW_  1000000
#define EWB_ 1000000
#define EC_  2000000

// ---------------- scratch (device globals; no allocation allowed) ----------
__device__ float g_qa[NA_*32], g_qp[NP_*32];
// interleaved k|v rows: 64 halfs (128B) per src node
__device__ __align__(32) __half g_kv0[NA_*64];   // authors as src (writes)
__device__ __align__(32) __half g_kv1[NP_*64];   // papers as src (written_by)
__device__ __align__(32) __half g_kv2[NP_*64];   // papers as src (cites)
__device__ float g_xa[NA_*32], g_xp[NP_*32];
__device__ float g_h1a[NA_*32], g_h1p[NP_*32];
__device__ __align__(32) __half g_x16a[NA_*128], g_x16p[NP_*128];
// CSR per relation (dst-indexed)
__device__ int g_deg_w[NP_], g_rp_w[NP_+1];  __device__ int g_cs_w[EW_];
__device__ int g_deg_b[NA_], g_rp_b[NA_+1];  __device__ int g_cs_b[EWB_];
__device__ int g_deg_c[NP_], g_rp_c[NP_+1];  __device__ int g_cs_c[EC_];
__device__ int g_bs_w[256], g_bs_b[256], g_bs_c[256];
// composite weights: 8 tasks x [32][KP<=128] fp16 (col-major B) + fp32 biases
__device__ __align__(32) __half g_Wt[8*32*128];
__device__ float g_bsv[8*32];

// ---------------- helpers ---------------------------------------------------
__device__ __forceinline__ unsigned long long pack2(float lo, float hi) {
    unsigned long long r;
    asm("mov.b64 %0, {%1,%2};" : "=l"(r) : "f"(lo), "f"(hi));
    return r;
}
__device__ __forceinline__ void ffma2(unsigned long long& acc,
                                      unsigned long long a, unsigned long long b) {
    asm("fma.rn.f32x2 %0, %1, %2, %0;" : "+l"(acc) : "l"(a), "l"(b));
}
__device__ __forceinline__ float2 unpack2(unsigned long long v) {
    float2 r;
    asm("mov.b64 {%0,%1}, %2;" : "=f"(r.x), "=f"(r.y) : "l"(v));
    return r;
}
static inline int divup(int a, int b) { return (a + b - 1) / b; }

// ---------------- fused CSR build ----------------------------------------------
struct Rel3 {
    const int *e0, *e1, *e2;
    int E0, E1, E2;
    int n0, n1, n2;
    int *deg0, *deg1, *deg2;
    int *rp0, *rp1, *rp2;
    int *cs0, *cs1, *cs2;
    int *bs0, *bs1, *bs2;
};

__global__ void zero_all_kernel(Rel3 R) {
    int i = blockIdx.x * blockDim.x + threadIdx.x;
    int t = R.n0 + R.n1 + R.n2;
    if (i >= t) return;
    if (i < R.n0) R.deg0[i] = 0;
    else if (i < R.n0 + R.n1) R.deg1[i - R.n0] = 0;
    else R.deg2[i - R.n0 - R.n1] = 0;
}
__global__ void count_all_kernel(Rel3 R) {
    int i = blockIdx.x * blockDim.x + threadIdx.x;
    if (i < R.E0) { atomicAdd(&R.deg0[__ldg(R.e0 + R.E0 + i)], 1); return; }
    i -= R.E0;
    if (i < R.E1) { atomicAdd(&R.deg1[__ldg(R.e1 + R.E1 + i)], 1); return; }
    i -= R.E1;
    if (i < R.E2) { atomicAdd(&R.deg2[__ldg(R.e2 + R.E2 + i)], 1); }
}
__device__ __forceinline__ void rel_sel(const Rel3& R, int r, const int*& deg, int& n, int*& bsum) {
    if (r == 0) { deg = R.deg0; n = R.n0; bsum = R.bs0; }
    else if (r == 1) { deg = R.deg1; n = R.n1; bsum = R.bs1; }
    else { deg = R.deg2; n = R.n2; bsum = R.bs2; }
}
__global__ void scan_p1_all(Rel3 R) {
    const int* deg; int n; int* bsum;
    rel_sel(R, blockIdx.y, deg, n, bsum);
    int base = blockIdx.x * 1024;
    if (base >= n) return;
    __shared__ int sm[256];
    int t = threadIdx.x;
    int s = 0;
#pragma unroll
    for (int j = 0; j < 4; j++) {
        int i = base + t * 4 + j;
        if (i < n) s += deg[i];
    }
    sm[t] = s; __syncthreads();
#pragma unroll
    for (int o = 128; o > 0; o >>= 1) {
        if (t < o) sm[t] += sm[t + o];
        __syncthreads();
    }
    if (t == 0) bsum[blockIdx.x] = sm[0];
}
__global__ void scan_p2_all(Rel3 R) {
    const int* degc; int n; int* bsum;
    rel_sel(R, blockIdx.x, degc, n, bsum);
    int* rp_last = (blockIdx.x == 0 ? R.rp0 : blockIdx.x == 1 ? R.rp1 : R.rp2) + n;
    int nb = (n + 1023) / 1024;
    __shared__ int sm[256];
    int t = threadIdx.x;
    int v = (t < nb) ? bsum[t] : 0;
    sm[t] = v; __syncthreads();
    for (int o = 1; o < 256; o <<= 1) {
        int x = (t >= o) ? sm[t - o] : 0;
        __syncthreads();
        sm[t] += x;
        __syncthreads();
    }
    if (t < nb) bsum[t] = sm[t] - v;
    if (t == 255) *rp_last = sm[255];
}
__global__ void scan_p3_all(Rel3 R) {
    const int* deg; int n; int* bsum;
    rel_sel(R, blockIdx.y, deg, n, bsum);
    int* rp  = (blockIdx.y == 0 ? R.rp0  : blockIdx.y == 1 ? R.rp1  : R.rp2);
    int* cur = (blockIdx.y == 0 ? R.deg0 : blockIdx.y == 1 ? R.deg1 : R.deg2);
    int base = blockIdx.x * 1024;
    if (base >= n) return;
    __shared__ int sm[256];
    int t = threadIdx.x;
    int v[4]; int s = 0;
#pragma unroll
    for (int j = 0; j < 4; j++) {
        int i = base + t * 4 + j;
        v[j] = (i < n) ? deg[i] : 0;
        s += v[j];
    }
    sm[t] = s; __syncthreads();
    for (int o = 1; o < 256; o <<= 1) {
        int x = (t >= o) ? sm[t - o] : 0;
        __syncthreads();
        sm[t] += x;
        __syncthreads();
    }
    int run = bsum[blockIdx.x] + sm[t] - s;
#pragma unroll
    for (int j = 0; j < 4; j++) {
        int i = base + t * 4 + j;
        if (i < n) { rp[i] = run; cur[i] = run; }
        run += v[j];
    }
}
__global__ void scatter_all_kernel(Rel3 R) {
    int i = blockIdx.x * blockDim.x + threadIdx.x;
    const int* e; int E; int* cur; int* cs;
    if (i < R.E0) { e = R.e0; E = R.E0; cur = R.deg0; cs = R.cs0; }
    else {
        i -= R.E0;
        if (i < R.E1) { e = R.e1; E = R.E1; cur = R.deg1; cs = R.cs1; }
        else {
            i -= R.E1;
            if (i >= R.E2) return;
            e = R.e2; E = R.E2; cur = R.deg2; cs = R.cs2;
        }
    }
    int slot = atomicAdd(&cur[__ldg(e + E + i)], 1);
    cs[slot] = __ldg(e + i);
}

// ---------------- weight composition (all 8 tasks, one launch) -----------------
struct CTask { const float* W; const float* b; const float* T; int prel_idx; };
struct CArgs { CTask t[8]; const float* prel; };

__global__ void compose_all_kernel(CArgs args, int F, int KP,
                                   __half* __restrict__ Wt, float* __restrict__ bs) {
    int task = blockIdx.y;
    int gw   = (blockIdx.x * blockDim.x + threadIdx.x) >> 5;
    int lane = threadIdx.x & 31;
    if (gw > KP) return;
    CTask tk = args.t[task];
    float scale = (tk.prel_idx >= 0) ? (__ldg(args.prel + tk.prel_idx) * 0.17677669529663687f) : 1.0f;
    if (gw == KP) {
        float rv = tk.b[lane];
        float acc;
        if (tk.T) {
            acc = 0.f;
#pragma unroll
            for (int j = 0; j < 32; j++) {
                float rj = __shfl_sync(0xffffffffu, rv, j);
                acc = fmaf(rj, __ldg(tk.T + j * 32 + lane), acc);
            }
        } else acc = rv;
        bs[task * 32 + lane] = acc * scale;
    } else if (gw >= F) {
        Wt[((size_t)task * 32 + lane) * KP + gw] = __float2half(0.f);
    } else {
        float rv = tk.W[(size_t)gw * 32 + lane];
        float acc;
        if (tk.T) {
            acc = 0.f;
#pragma unroll
            for (int j = 0; j < 32; j++) {
                float rj = __shfl_sync(0xffffffffu, rv, j);
                acc = fmaf(rj, __ldg(tk.T + j * 32 + lane), acc);
            }
        } else acc = rv;
        Wt[((size_t)task * 32 + lane) * KP + gw] = __float2half(acc * scale);
    }
}

// ---------------- fp32 -> fp16 conversion --------------------------------------
__global__ void cvt16_kernel(const float* __restrict__ x, __half* __restrict__ y,
                             int n, int F, int KP) {
    int i = blockIdx.x * blockDim.x + threadIdx.x;
    int cpr = KP >> 2;
    int total = n * cpr;
    if (i >= total) return;
    int node = i / cpr;
    int c4 = (i % cpr) << 2;
    float4 v = (c4 < F) ? __ldg((const float4*)(x + (size_t)node * F + c4))
                        : make_float4(0.f, 0.f, 0.f, 0.f);
    __half2 h0 = __floats2half2_rn(v.x, v.y);
    __half2 h1 = __floats2half2_rn(v.z, v.w);
    __half2* dst = (__half2*)(y + (size_t)node * KP + c4);
    dst[0] = h0; dst[1] = h1;
}

// ---------------- wmma (HMMA) projection ---------------------------------------
// Block = 256 thr (8 warps) = 128 nodes; warp = 16-node m-tile. mat0 -> q fp32
// (row stride 32); mats 1.. -> fp16 with ROW STRIDE 64 (interleaved kv halves).
template<int KP, int NMAT>
__global__ void __launch_bounds__(256) proj_wmma_kernel(
        const __half* __restrict__ x16, const __half* __restrict__ Wt,
        const float* __restrict__ bias,
        float* __restrict__ qout,
        __half* __restrict__ o1, __half* __restrict__ o2,
        __half* __restrict__ o3, __half* __restrict__ o4, int n) {
    extern __shared__ __align__(32) char smem[];
    float* bsf   = (float*)smem;
    float* stage = (float*)(smem + NMAT * 32 * 4);
    __half* sA   = (__half*)(smem + NMAT * 32 * 4 + 8 * 16 * 32 * 4);
    const int LDA = KP + 8;
    int tid = threadIdx.x, wid = tid >> 5, lane = tid & 31;
    int base = blockIdx.x * 128;

    if (tid < NMAT * 32) bsf[tid] = __ldg(bias + tid);
    const int CH = KP / 8;
    for (int idx = tid; idx < 128 * CH; idx += 256) {
        int row = idx / CH, c8 = (idx % CH) * 8;
        uint4 val = make_uint4(0, 0, 0, 0);
        if (base + row < n) val = *(const uint4*)(x16 + (size_t)(base + row) * KP + c8);
        *(uint4*)(sA + row * LDA + c8) = val;
    }
    __syncthreads();

    using namespace nvcuda;
    float* stW = stage + wid * 16 * 32;
    int m0 = wid * 16;
    __half* outs[4] = {o1, o2, o3, o4};
    int row = lane >> 1, c0 = (lane & 1) * 16;
    int node = base + m0 + row;
    bool store = (node < n);

#pragma unroll
    for (int mat = 0; mat < NMAT; mat++) {
        wmma::fragment<wmma::accumulator, 16, 16, 16, float> acc0, acc1;
        wmma::fill_fragment(acc0, 0.f);
        wmma::fill_fragment(acc1, 0.f);
        const __half* Wm = Wt + (size_t)mat * 32 * KP;
#pragma unroll
        for (int k0 = 0; k0 < KP; k0 += 16) {
            wmma::fragment<wmma::matrix_a, 16, 16, 16, __half, wmma::row_major> fa;
            wmma::fragment<wmma::matrix_b, 16, 16, 16, __half, wmma::col_major> fb0, fb1;
            wmma::load_matrix_sync(fa, sA + m0 * LDA + k0, LDA);
            wmma::load_matrix_sync(fb0, Wm + k0, KP);
            wmma::load_matrix_sync(fb1, Wm + 16 * KP + k0, KP);
            wmma::mma_sync(acc0, fa, fb0, acc0);
            wmma::mma_sync(acc1, fa, fb1, acc1);
        }
        wmma::store_matrix_sync(stW,      acc0, 32, wmma::mem_row_major);
        wmma::store_matrix_sync(stW + 16, acc1, 32, wmma::mem_row_major);
        __syncwarp();
        if (store) {
            if (mat == 0) {
                float4* dst = (float4*)(qout + (size_t)node * 32 + c0);
#pragma unroll
                for (int g = 0; g < 4; g++) {
                    float4 f;
                    f.x = stW[row * 32 + c0 + 4*g + 0] + bsf[c0 + 4*g + 0];
                    f.y = stW[row * 32 + c0 + 4*g + 1] + bsf[c0 + 4*g + 1];
                    f.z = stW[row * 32 + c0 + 4*g + 2] + bsf[c0 + 4*g + 2];
                    f.w = stW[row * 32 + c0 + 4*g + 3] + bsf[c0 + 4*g + 3];
                    dst[g] = f;
                }
            } else {
                uint32_t p[8];
#pragma unroll
                for (int c = 0; c < 8; c++) {
                    float lo = stW[row * 32 + c0 + 2*c]     + bsf[mat * 32 + c0 + 2*c];
                    float hi = stW[row * 32 + c0 + 2*c + 1] + bsf[mat * 32 + c0 + 2*c + 1];
                    __half2 h = __floats2half2_rn(lo, hi);
                    p[c] = *(uint32_t*)&h;
                }
                // interleaved kv: row stride 64 halfs
                uint4* dst = (uint4*)(outs[mat - 1] + (size_t)node * 64 + c0);
                dst[0] = make_uint4(p[0], p[1], p[2], p[3]);
                dst[1] = make_uint4(p[4], p[5], p[6], p[7]);
            }
        }
        __syncwarp();
    }
}

// ---------------- dst-centric edge aggregation (no atomics, fp16 kv) -----------
// 4 lanes per dst node, 8 dst per warp. kv interleaved (1 cacheline/edge).
// Unroll-by-4 over edges for MLP.
__device__ __forceinline__ float edge_score(const uint4& kh, const float4& q0, const float4& q1) {
    float2 k0 = __half22float2(*(const __half2*)&kh.x);
    float2 k1 = __half22float2(*(const __half2*)&kh.y);
    float2 k2 = __half22float2(*(const __half2*)&kh.z);
    float2 k3 = __half22float2(*(const __half2*)&kh.w);
    return q0.x*k0.x + q0.y*k0.y + q0.z*k1.x + q0.w*k1.y
         + q1.x*k2.x + q1.y*k2.y + q1.z*k3.x + q1.w*k3.y;
}
__device__ __forceinline__ void edge_accum(unsigned long long acc[4], const uint4& vh, float ex) {
    unsigned long long ex2 = pack2(ex, ex);
    float2 v0 = __half22float2(*(const __half2*)&vh.x);
    float2 v1 = __half22float2(*(const __half2*)&vh.y);
    float2 v2 = __half22float2(*(const __half2*)&vh.z);
    float2 v3 = __half22float2(*(const __half2*)&vh.w);
    ffma2(acc[0], pack2(v0.x, v0.y), ex2);
    ffma2(acc[1], pack2(v1.x, v1.y), ex2);
    ffma2(acc[2], pack2(v2.x, v2.y), ex2);
    ffma2(acc[3], pack2(v3.x, v3.y), ex2);
}
__device__ __forceinline__ float accum_rel_h(int b0, int b1, const int* __restrict__ cs,
                                             const __half* __restrict__ kv,
                                             const float4& q0, const float4& q1,
                                             unsigned gmask, int ql,
                                             unsigned long long acc[4]) {
    float den = 0.f;
    int e = b0;
    for (; e + 4 <= b1; e += 4) {
        int s0 = __ldg(cs + e);
        int s1 = __ldg(cs + e + 1);
        int s2 = __ldg(cs + e + 2);
        int s3 = __ldg(cs + e + 3);
        const uint4* r0 = (const uint4*)(kv + (size_t)s0 * 64);
        const uint4* r1 = (const uint4*)(kv + (size_t)s1 * 64);
        const uint4* r2 = (const uint4*)(kv + (size_t)s2 * 64);
        const uint4* r3 = (const uint4*)(kv + (size_t)s3 * 64);
        uint4 k0 = __ldg(r0 + ql),     k1 = __ldg(r1 + ql);
        uint4 k2 = __ldg(r2 + ql),     k3 = __ldg(r3 + ql);
        uint4 v0 = __ldg(r0 + 4 + ql), v1 = __ldg(r1 + 4 + ql);
        uint4 v2 = __ldg(r2 + 4 + ql), v3 = __ldg(r3 + 4 + ql);
        float sc0 = edge_score(k0, q0, q1);
        float sc1 = edge_score(k1, q0, q1);
        float sc2 = edge_score(k2, q0, q1);
        float sc3 = edge_score(k3, q0, q1);
        sc0 += __shfl_xor_sync(gmask, sc0, 1);
        sc1 += __shfl_xor_sync(gmask, sc1, 1);
        sc2 += __shfl_xor_sync(gmask, sc2, 1);
        sc3 += __shfl_xor_sync(gmask, sc3, 1);
        sc0 += __shfl_xor_sync(gmask, sc0, 2);
        sc1 += __shfl_xor_sync(gmask, sc1, 2);
        sc2 += __shfl_xor_sync(gmask, sc2, 2);
        sc3 += __shfl_xor_sync(gmask, sc3, 2);
        float ex0 = __expf(fminf(sc0, 60.0f));
        float ex1 = __expf(fminf(sc1, 60.0f));
        float ex2 = __expf(fminf(sc2, 60.0f));
        float ex3 = __expf(fminf(sc3, 60.0f));
        edge_accum(acc, v0, ex0);
        edge_accum(acc, v1, ex1);
        edge_accum(acc, v2, ex2);
        edge_accum(acc, v3, ex3);
        den += (ex0 + ex1) + (ex2 + ex3);
    }
    for (; e < b1; e++) {
        int s0 = __ldg(cs + e);
        const uint4* r0 = (const uint4*)(kv + (size_t)s0 * 64);
        uint4 k0 = __ldg(r0 + ql);
        uint4 v0 = __ldg(r0 + 4 + ql);
        float sc0 = edge_score(k0, q0, q1);
        sc0 += __shfl_xor_sync(gmask, sc0, 1);
        sc0 += __shfl_xor_sync(gmask, sc0, 2);
        float ex0 = __expf(fminf(sc0, 60.0f));
        edge_accum(acc, v0, ex0);
        den += ex0;
    }
    return den;
}
__global__ void agg1_kernel(const int* __restrict__ rp, const int* __restrict__ cs,
                            const float* __restrict__ q, const __half* __restrict__ kv,
                            float* __restrict__ xout, int n) {
    int gw   = (blockIdx.x * blockDim.x + threadIdx.x) >> 5;
    int lane = threadIdx.x & 31;
    int sub  = lane >> 2;
    int ql   = lane & 3;
    unsigned gmask = 0xFu << (sub * 4);
    int d = gw * 8 + sub;
    bool valid = (d < n);
    int dd = valid ? d : (n - 1);
    int b0 = __ldg(rp + dd);
    int b1 = valid ? __ldg(rp + dd + 1) : b0;
    float4 q0 = __ldg((const float4*)(q + (size_t)dd * 32) + ql * 2);
    float4 q1 = __ldg((const float4*)(q + (size_t)dd * 32) + ql * 2 + 1);
    unsigned long long acc[4];
    acc[0] = acc[1] = acc[2] = acc[3] = pack2(0.f, 0.f);
    float den = accum_rel_h(b0, b1, cs, kv, q0, q1, gmask, ql, acc);
    if (valid) {
        float inv = (den > 0.f) ? (1.0f / den) : 0.0f;
        float2 a0 = unpack2(acc[0]), a1 = unpack2(acc[1]);
        float2 a2 = unpack2(acc[2]), a3 = unpack2(acc[3]);
        *((float4*)(xout + (size_t)d * 32) + ql * 2)     = make_float4(a0.x*inv, a0.y*inv, a1.x*inv, a1.y*inv);
        *((float4*)(xout + (size_t)d * 32) + ql * 2 + 1) = make_float4(a2.x*inv, a2.y*inv, a3.x*inv, a3.y*inv);
    }
}
__global__ void agg2_kernel(const int* __restrict__ rp1, const int* __restrict__ cs1,
                            const __half* __restrict__ kvA,
                            const int* __restrict__ rp2, const int* __restrict__ cs2,
                            const __half* __restrict__ kvB,
                            const float* __restrict__ q,
                            float* __restrict__ xout, int n) {
    int gw   = (blockIdx.x * blockDim.x + threadIdx.x) >> 5;
    int lane = threadIdx.x & 31;
    int sub  = lane >> 2;
    int ql   = lane & 3;
    unsigned gmask = 0xFu << (sub * 4);
    int d = gw * 8 + sub;
    bool valid = (d < n);
    int dd = valid ? d : (n - 1);
    float4 q0 = __ldg((const float4*)(q + (size_t)dd * 32) + ql * 2);
    float4 q1 = __ldg((const float4*)(q + (size_t)dd * 32) + ql * 2 + 1);
    int a0 = __ldg(rp1 + dd);
    int a1 = valid ? __ldg(rp1 + dd + 1) : a0;
    int c0 = __ldg(rp2 + dd);
    int c1 = valid ? __ldg(rp2 + dd + 1) : c0;
    unsigned long long accA[4], accB[4];
    accA[0]=accA[1]=accA[2]=accA[3]=pack2(0.f,0.f);
    accB[0]=accB[1]=accB[2]=accB[3]=pack2(0.f,0.f);
    float denA = accum_rel_h(a0, a1, cs1, kvA, q0, q1, gmask, ql, accA);
    float denB = accum_rel_h(c0, c1, cs2, kvB, q0, q1, gmask, ql, accB);
    if (valid) {
        float invA = (denA > 0.f) ? (1.0f / denA) : 0.0f;
        float invB = (denB > 0.f) ? (1.0f / denB) : 0.0f;
        float2 rA[4], rB[4];
#pragma unroll
        for (int i = 0; i < 4; i++) { rA[i] = unpack2(accA[i]); rB[i] = unpack2(accB[i]); }
        *((float4*)(xout + (size_t)d * 32) + ql * 2) =
            make_float4(rA[0].x*invA + rB[0].x*invB, rA[0].y*invA + rB[0].y*invB,
                        rA[1].x*invA + rB[1].x*invB, rA[1].y*invA + rB[1].y*invB);
        *((float4*)(xout + (size_t)d * 32) + ql * 2 + 1) =
            make_float4(rA[2].x*invA + rB[2].x*invB, rA[2].y*invA + rB[2].y*invB,
                        rA[3].x*invA + rB[3].x*invB, rA[3].y*invA + rB[3].y*invB);
    }
}

// ---------------- output transform ---------------------------------------------
// Optional out16: fp16 copy of the output (feeds next layer's projection input).
__global__ void out_kernel(const float* __restrict__ x1,
                           const float* __restrict__ Wa, const float* __restrict__ ba,
                           const float* __restrict__ skipv, int t_idx,
                           const float* __restrict__ xin,
                           float* __restrict__ out, __half* __restrict__ out16,
                           int n, int use_skip) {
    __shared__ float sW[1024];
    for (int i = threadIdx.x; i < 1024; i += blockDim.x) sW[i] = Wa[i];
    __syncthreads();
    int lane = threadIdx.x & 31;
    int gw = blockIdx.x * (blockDim.x >> 5) + (threadIdx.x >> 5);
    int n0 = gw * 4;
    if (n0 >= n) return;
    int m = n - n0; if (m > 4) m = 4;

    float4 xr[4];
#pragma unroll
    for (int j = 0; j < 4; j++) {
        if (j < m && lane < 8) {
            float4 a = __ldg((const float4*)(x1 + (size_t)(n0 + j) * 32) + lane);
            a.x = 0.5f * a.x * (1.0f + erff(a.x * 0.7071067811865475f));
            a.y = 0.5f * a.y * (1.0f + erff(a.y * 0.7071067811865475f));
            a.z = 0.5f * a.z * (1.0f + erff(a.z * 0.7071067811865475f));
            a.w = 0.5f * a.w * (1.0f + erff(a.w * 0.7071067811865475f));
            xr[j] = a;
        } else {
            xr[j] = make_float4(0.f, 0.f, 0.f, 0.f);
        }
    }
    unsigned long long A01 = pack2(ba[lane], ba[lane]), A23 = A01;
    for (int i0 = 0; i0 < 32; i0 += 4) {
        int sl = i0 >> 2;
        float xs[4][4];
#pragma unroll
        for (int j = 0; j < 4; j++) {
            xs[j][0] = __shfl_sync(0xffffffffu, xr[j].x, sl);
            xs[j][1] = __shfl_sync(0xffffffffu, xr[j].y, sl);
            xs[j][2] = __shfl_sync(0xffffffffu, xr[j].z, sl);
            xs[j][3] = __shfl_sync(0xffffffffu, xr[j].w, sl);
        }
#pragma unroll
        for (int c = 0; c < 4; c++) {
            float w = sW[(i0 + c) * 32 + lane];
            unsigned long long w2 = pack2(w, w);
            ffma2(A01, pack2(xs[0][c], xs[1][c]), w2);
            ffma2(A23, pack2(xs[2][c], xs[3][c]), w2);
        }
    }
    float2 a01 = unpack2(A01), a23 = unpack2(A23);
    float o[4] = {a01.x, a01.y, a23.x, a23.y};
    if (use_skip) {
        float a = 1.0f / (1.0f + expf(-__ldg(skipv + t_idx)));
#pragma unroll
        for (int j = 0; j < 4; j++) {
            if (j < m)
                o[j] = a * o[j] + (1.0f - a) * __ldg(xin + (size_t)(n0 + j) * 32 + lane);
        }
    }
#pragma unroll
    for (int j = 0; j < 4; j++) {
        if (j < m) {
            out[(size_t)(n0 + j) * 32 + lane] = o[j];
            if (out16) out16[(size_t)(n0 + j) * 32 + lane] = __float2half(o[j]);
        }
    }
}

// ---------------- host orchestration ----------------------------------------
struct LayerW {
    const float *Wk, *bk, *Wq, *bq, *Wv, *bv, *Wa, *ba, *skip, *arel, *mrel, *prel;
};

template<int KP>
static void run_layer(const __half* x16a, const __half* x16p, int F,
                      const LayerW& L, int use_skip,
                      const float* xa_skip, const float* xp_skip,
                      float* outa, float* outp, __half* outa16, __half* outp16,
                      float* qa, float* qp,
                      __half* kv0, __half* kv1, __half* kv2,
                      float* xa_agg, float* xp_agg,
                      const int* rp_w, const int* cs_w,
                      const int* rp_b, const int* cs_b,
                      const int* rp_c, const int* cs_c,
                      __half* Wt, float* bs) {
    const int BT = 256;
    int wsz = F * 32;
    CArgs ca;
    ca.prel = L.prel;
    ca.t[0] = { L.Wq,       L.bq,      (const float*)0, -1 };   // q authors
    ca.t[1] = { L.Wk,       L.bk,      L.arel + 0,      0  };   // k0
    ca.t[2] = { L.Wv,       L.bv,      L.mrel + 0,      -1 };   // v0
    ca.t[3] = { L.Wq + wsz, L.bq + 32, (const float*)0, -1 };   // q papers
    ca.t[4] = { L.Wk + wsz, L.bk + 32, L.arel + 1024,   1  };   // k1
    ca.t[5] = { L.Wv + wsz, L.bv + 32, L.mrel + 1024,   -1 };   // v1
    ca.t[6] = { L.Wk + wsz, L.bk + 32, L.arel + 2048,   2  };   // k2
    ca.t[7] = { L.Wv + wsz, L.bv + 32, L.mrel + 2048,   -1 };   // v2
    dim3 cg(divup((KP + 1) * 32, BT), 8);
    compose_all_kernel<<<cg, BT>>>(ca, F, KP, Wt, bs);

    int smem_a = 3 * 32 * 4 + 8 * 16 * 32 * 4 + 128 * (KP + 8) * 2;
    int smem_p = 5 * 32 * 4 + 8 * 16 * 32 * 4 + 128 * (KP + 8) * 2;
    proj_wmma_kernel<KP, 3><<<divup(NA_, 128), 256, smem_a>>>(
        x16a, Wt, bs, qa, kv0, kv0 + 32, (__half*)0, (__half*)0, NA_);
    proj_wmma_kernel<KP, 5><<<divup(NP_, 128), 256, smem_p>>>(
        x16p, Wt + (size_t)3 * 32 * KP, bs + 3 * 32, qp,
        kv1, kv1 + 32, kv2, kv2 + 32, NP_);

    int gaA = divup(NA_, 64), gpA = divup(NP_, 64);
    agg2_kernel<<<gpA, BT>>>(rp_w, cs_w, kv0, rp_c, cs_c, kv2, qp, xp_agg, NP_);
    agg1_kernel<<<gaA, BT>>>(rp_b, cs_b, qa, kv1, xa_agg, NA_);

    int ga4 = divup(divup(NA_, 4) * 32, BT);
    int gp4 = divup(divup(NP_, 4) * 32, BT);
    out_kernel<<<ga4, BT>>>(xa_agg, L.Wa,        L.ba,      L.skip, 0, xa_skip, outa, outa16, NA_, use_skip);
    out_kernel<<<gp4, BT>>>(xp_agg, L.Wa + 1024, L.ba + 32, L.skip, 1, xp_skip, outp, outp16, NP_, use_skip);
}

extern "C" void kernel_launch(void* const* d_in, const int* in_sizes, int n_in,
                              void* d_out, int out_size) {
    const float* x_a   = (const float*)d_in[0];
    const float* x_p   = (const float*)d_in[1];
    const int* e_wr    = (const int*)d_in[2];
    const int* e_wb    = (const int*)d_in[3];
    const int* e_ci    = (const int*)d_in[4];
    LayerW L1 = { (const float*)d_in[5],  (const float*)d_in[6],
                  (const float*)d_in[7],  (const float*)d_in[8],
                  (const float*)d_in[9],  (const float*)d_in[10],
                  (const float*)d_in[11], (const float*)d_in[12],
                  (const float*)d_in[13], (const float*)d_in[14],
                  (const float*)d_in[15], (const float*)d_in[16] };
    LayerW L2 = { (const float*)d_in[17], (const float*)d_in[18],
                  (const float*)d_in[19], (const float*)d_in[20],
                  (const float*)d_in[21], (const float*)d_in[22],
                  (const float*)d_in[23], (const float*)d_in[24],
                  (const float*)d_in[25], (const float*)d_in[26],
                  (const float*)d_in[27], (const float*)d_in[28] };

    float *qa,*qp,*xa_agg,*xp_agg,*h1a,*h1p,*bs;
    __half *kv0,*kv1,*kv2,*x16a,*x16p,*Wt;
    cudaGetSymbolAddress((void**)&qa, g_qa);   cudaGetSymbolAddress((void**)&qp, g_qp);
    cudaGetSymbolAddress((void**)&kv0, g_kv0);
    cudaGetSymbolAddress((void**)&kv1, g_kv1);
    cudaGetSymbolAddress((void**)&kv2, g_kv2);
    cudaGetSymbolAddress((void**)&xa_agg, g_xa);
    cudaGetSymbolAddress((void**)&xp_agg, g_xp);
    cudaGetSymbolAddress((void**)&h1a, g_h1a); cudaGetSymbolAddress((void**)&h1p, g_h1p);
    cudaGetSymbolAddress((void**)&x16a, g_x16a); cudaGetSymbolAddress((void**)&x16p, g_x16p);
    cudaGetSymbolAddress((void**)&Wt, g_Wt);   cudaGetSymbolAddress((void**)&bs, g_bsv);

    Rel3 R;
    R.e0 = e_ci; R.E0 = EC_;  R.n0 = NP_;
    R.e1 = e_wr; R.E1 = EW_;  R.n1 = NP_;
    R.e2 = e_wb; R.E2 = EWB_; R.n2 = NA_;
    cudaGetSymbolAddress((void**)&R.deg0, g_deg_c); cudaGetSymbolAddress((void**)&R.rp0, g_rp_c);
    cudaGetSymbolAddress((void**)&R.cs0, g_cs_c);   cudaGetSymbolAddress((void**)&R.bs0, g_bs_c);
    cudaGetSymbolAddress((void**)&R.deg1, g_deg_w); cudaGetSymbolAddress((void**)&R.rp1, g_rp_w);
    cudaGetSymbolAddress((void**)&R.cs1, g_cs_w);   cudaGetSymbolAddress((void**)&R.bs1, g_bs_w);
    cudaGetSymbolAddress((void**)&R.deg2, g_deg_b); cudaGetSymbolAddress((void**)&R.rp2, g_rp_b);
    cudaGetSymbolAddress((void**)&R.cs2, g_cs_b);   cudaGetSymbolAddress((void**)&R.bs2, g_bs_b);

    cudaFuncSetAttribute(proj_wmma_kernel<128,3>, cudaFuncAttributeMaxDynamicSharedMemorySize,
                         3*32*4 + 8*16*32*4 + 128*(128+8)*2);
    cudaFuncSetAttribute(proj_wmma_kernel<128,5>, cudaFuncAttributeMaxDynamicSharedMemorySize,
                         5*32*4 + 8*16*32*4 + 128*(128+8)*2);

    const int BT = 256;
    // fused CSR build (6 launches for all 3 relations)
    int totE = EC_ + EW_ + EWB_;
    int totN = NP_ + NP_ + NA_;
    int nbmax = divup(NP_, 1024);
    zero_all_kernel<<<divup(totN, BT), BT>>>(R);
    count_all_kernel<<<divup(totE, BT), BT>>>(R);
    scan_p1_all<<<dim3(nbmax, 3), 256>>>(R);
    scan_p2_all<<<3, 256>>>(R);
    scan_p3_all<<<dim3(nbmax, 3), 256>>>(R);
    scatter_all_kernel<<<divup(totE, BT), BT>>>(R);

    // Layer 1 inputs -> fp16 (KP = 128)
    cvt16_kernel<<<divup(NA_*32, BT), BT>>>(x_a, x16a, NA_, 128, 128);
    cvt16_kernel<<<divup(NP_*32, BT), BT>>>(x_p, x16p, NP_, 128, 128);
    // Layer 1: 128 -> 32, no skip. out_kernel also emits fp16 copy for layer 2.
    run_layer<128>(x16a, x16p, 128, L1, 0, x_a, x_p, h1a, h1p, x16a, x16p,
                   qa, qp, kv0, kv1, kv2, xa_agg, xp_agg,
                   R.rp1, R.cs1, R.rp2, R.cs2, R.rp0, R.cs0, Wt, bs);

    // Layer 2: 32 -> 32, gated skip (x16 already prepared by layer-1 out kernels).
    float* out = (float*)d_out;
    run_layer<32>(x16a, x16p, 32, L2, 1, h1a, h1p,
                  out, out + (size_t)NA_ * 32, (__half*)0, (__half*)0,
                  qa, qp, kv0, kv1, kv2, xa_agg, xp_agg,
                  R.rp1, R.cs1, R.rp2, R.cs2, R.rp0, R.cs0, Wt, bs);
}